// round 1
// baseline (speedup 1.0000x reference)
#include <cuda_runtime.h>

#define B_ 2
#define H_ 16
#define N_ 2048
#define D_ 64
#define HG 8
#define HL 8
#define W_ 64
#define SCALE 0.125f
#define NEGV (-1e12f)

// Scratch (allocation-free rule: __device__ globals)
__device__ float d_scores[(size_t)B_ * HG * N_ * N_];   // 256 MB: masked+scaled scores for global heads
__device__ float d_m[B_ * HG * N_];
__device__ float d_l[B_ * HG * N_];
__device__ int   d_mask[B_ * N_];

// ---------------------------------------------------------------------------
// Mask canonicalization: detect storage dtype (int32 / float32 / uint8) by
// pattern, convert to int 0/1. Deterministic for fixed bench inputs.
// ---------------------------------------------------------------------------
__global__ void prep_mask_kernel(const void* __restrict__ mraw) {
    __shared__ int mode;
    if (threadIdx.x == 0) {
        const unsigned int* w = (const unsigned int*)mraw;
        bool is_int = true, is_float = true;
        for (int i = 0; i < 64; i++) {
            unsigned int v = w[i];
            if (v > 1u) is_int = false;
            if (v != 0u && v != 0x3F800000u) is_float = false;
        }
        mode = is_int ? 1 : (is_float ? 2 : 0);
    }
    __syncthreads();
    int m = mode;
    for (int i = threadIdx.x; i < B_ * N_; i += blockDim.x) {
        int val;
        if (m == 1)      val = (((const int*)mraw)[i] != 0);
        else if (m == 2) val = (((const float*)mraw)[i] != 0.0f);
        else             val = (((const unsigned char*)mraw)[i] != 0);
        d_mask[i] = val;
    }
}

// ---------------------------------------------------------------------------
// Global heads pass 1: S = scale * Q K^T (masked -> NEGV), online (m, l),
// spill S to scratch. Block = 256 threads = 16x16 grid, 4x4 microtile,
// tile = 64 q rows x 64 k cols, loop over 32 k-tiles.
// Smem tiles padded to stride 65 -> conflict-free scalar LDS in microkernel.
// ---------------------------------------------------------------------------
__global__ void __launch_bounds__(256) gpass1_kernel(const float* __restrict__ Qm,
                                                     const float* __restrict__ Km) {
    __shared__ float Qs[64 * 65];
    __shared__ float Ks[64 * 65];
    const int b = blockIdx.z, h = blockIdx.y, q0 = blockIdx.x * 64;
    const float* Qp = Qm + ((size_t)(b * H_ + h) * N_ + q0) * D_;
    const float* Kp = Km + (size_t)(b * H_ + h) * N_ * D_;
    const int tid = threadIdx.x;
    const int ty = tid >> 4, tx = tid & 15;

    for (int c = tid; c < 64 * 16; c += 256) {
        int r = c >> 4, d4 = (c & 15) << 2;
        float4 v = *(const float4*)(Qp + r * D_ + d4);
        float* dst = Qs + r * 65 + d4;
        dst[0] = v.x; dst[1] = v.y; dst[2] = v.z; dst[3] = v.w;
    }

    float m[4], l[4];
#pragma unroll
    for (int i = 0; i < 4; i++) { m[i] = NEGV; l[i] = 0.0f; }

    const int mrow = b * N_;
    const size_t srow0 = ((size_t)(b * HG + h) * N_ + q0) * N_;

    for (int kt = 0; kt < N_ / 64; kt++) {
        __syncthreads();
        const float* Kt = Kp + (size_t)kt * 64 * D_;
        for (int c = tid; c < 64 * 16; c += 256) {
            int r = c >> 4, d4 = (c & 15) << 2;
            float4 v = *(const float4*)(Kt + r * D_ + d4);
            float* dst = Ks + r * 65 + d4;
            dst[0] = v.x; dst[1] = v.y; dst[2] = v.z; dst[3] = v.w;
        }
        __syncthreads();

        float s[4][4];
#pragma unroll
        for (int i = 0; i < 4; i++)
#pragma unroll
            for (int j = 0; j < 4; j++) s[i][j] = 0.0f;

#pragma unroll 8
        for (int d = 0; d < 64; d++) {
            float qv[4], kv[4];
#pragma unroll
            for (int i = 0; i < 4; i++) qv[i] = Qs[(ty * 4 + i) * 65 + d];
#pragma unroll
            for (int j = 0; j < 4; j++) kv[j] = Ks[(tx * 4 + j) * 65 + d];
#pragma unroll
            for (int i = 0; i < 4; i++)
#pragma unroll
                for (int j = 0; j < 4; j++) s[i][j] += qv[i] * kv[j];
        }

        // scale + mask
        const int kbase = kt * 64 + tx * 4;
#pragma unroll
        for (int j = 0; j < 4; j++) {
            bool mk = (d_mask[mrow + kbase + j] != 0);
#pragma unroll
            for (int i = 0; i < 4; i++)
                s[i][j] = mk ? s[i][j] * SCALE : NEGV;
        }

        // online softmax stats per row (16-lane groups = same ty)
#pragma unroll
        for (int i = 0; i < 4; i++) {
            float tmax = fmaxf(fmaxf(s[i][0], s[i][1]), fmaxf(s[i][2], s[i][3]));
#pragma unroll
            for (int o = 8; o >= 1; o >>= 1)
                tmax = fmaxf(tmax, __shfl_xor_sync(0xffffffffu, tmax, o));
            float nm = fmaxf(m[i], tmax);
            float es = __expf(s[i][0] - nm) + __expf(s[i][1] - nm) +
                       __expf(s[i][2] - nm) + __expf(s[i][3] - nm);
#pragma unroll
            for (int o = 8; o >= 1; o >>= 1)
                es += __shfl_xor_sync(0xffffffffu, es, o);
            l[i] = l[i] * __expf(m[i] - nm) + es;
            m[i] = nm;
            float4 sv = make_float4(s[i][0], s[i][1], s[i][2], s[i][3]);
            *(float4*)(&d_scores[srow0 + (size_t)(ty * 4 + i) * N_ + kbase]) = sv;
        }
    }

    if (tx == 0) {
#pragma unroll
        for (int i = 0; i < 4; i++) {
            int rid = (b * HG + h) * N_ + q0 + ty * 4 + i;
            d_m[rid] = m[i];
            d_l[rid] = l[i];
        }
    }
}

// ---------------------------------------------------------------------------
// Global heads pass 2: p = exp(s - m)/l (write p_g), out = p @ V.
// Same 16x16 / 4x4 microtile structure; P staged transposed in smem for PV.
// ---------------------------------------------------------------------------
__global__ void __launch_bounds__(256) gpass2_kernel(const float* __restrict__ Vm,
                                                     float* __restrict__ outp,
                                                     float* __restrict__ pg) {
    __shared__ float Vs[64 * 65];        // [k][d]
    __shared__ float Ps[64 * 65];        // [k][q]
    const int b = blockIdx.z, h = blockIdx.y, q0 = blockIdx.x * 64;
    const float* Vp = Vm + (size_t)(b * H_ + h) * N_ * D_;
    const int tid = threadIdx.x;
    const int ty = tid >> 4, tx = tid & 15;

    float m[4], invl[4];
#pragma unroll
    for (int i = 0; i < 4; i++) {
        int rid = (b * HG + h) * N_ + q0 + ty * 4 + i;
        m[i] = d_m[rid];
        invl[i] = 1.0f / d_l[rid];
    }

    float o[4][4];
#pragma unroll
    for (int i = 0; i < 4; i++)
#pragma unroll
        for (int j = 0; j < 4; j++) o[i][j] = 0.0f;

    const size_t srow0 = ((size_t)(b * HG + h) * N_ + q0) * N_;

    for (int kt = 0; kt < N_ / 64; kt++) {
        __syncthreads();
        const float* Vt = Vp + (size_t)kt * 64 * D_;
        for (int c = tid; c < 64 * 16; c += 256) {
            int r = c >> 4, d4 = (c & 15) << 2;
            float4 v = *(const float4*)(Vt + r * D_ + d4);
            float* dst = Vs + r * 65 + d4;
            dst[0] = v.x; dst[1] = v.y; dst[2] = v.z; dst[3] = v.w;
        }
        const int kbase = kt * 64 + tx * 4;
#pragma unroll
        for (int i = 0; i < 4; i++) {
            size_t idx = srow0 + (size_t)(ty * 4 + i) * N_ + kbase;
            float4 sv = *(const float4*)(&d_scores[idx]);
            float4 pv;
            pv.x = __expf(sv.x - m[i]) * invl[i];
            pv.y = __expf(sv.y - m[i]) * invl[i];
            pv.z = __expf(sv.z - m[i]) * invl[i];
            pv.w = __expf(sv.w - m[i]) * invl[i];
            *(float4*)(&pg[idx]) = pv;
            Ps[(tx * 4 + 0) * 65 + ty * 4 + i] = pv.x;
            Ps[(tx * 4 + 1) * 65 + ty * 4 + i] = pv.y;
            Ps[(tx * 4 + 2) * 65 + ty * 4 + i] = pv.z;
            Ps[(tx * 4 + 3) * 65 + ty * 4 + i] = pv.w;
        }
        __syncthreads();

#pragma unroll 8
        for (int k = 0; k < 64; k++) {
            float pv[4], vv[4];
#pragma unroll
            for (int i = 0; i < 4; i++) pv[i] = Ps[k * 65 + ty * 4 + i];
#pragma unroll
            for (int j = 0; j < 4; j++) vv[j] = Vs[k * 65 + tx * 4 + j];
#pragma unroll
            for (int i = 0; i < 4; i++)
#pragma unroll
                for (int j = 0; j < 4; j++) o[i][j] += pv[i] * vv[j];
        }
    }

#pragma unroll
    for (int i = 0; i < 4; i++) {
        float4 ov = make_float4(o[i][0], o[i][1], o[i][2], o[i][3]);
        *(float4*)(&outp[((size_t)(b * H_ + h) * N_ + q0 + ty * 4 + i) * D_ + tx * 4]) = ov;
    }
}

// ---------------------------------------------------------------------------
// Local (banded) heads: one warp per q row, 8 rows per block.
// Band tile (136 keys) staged in one smem buffer, K phase then V phase.
// Full p_l rows written (band values + zeros) -> fused zero-fill.
// ---------------------------------------------------------------------------
__global__ void __launch_bounds__(256) local_kernel(const float* __restrict__ Qm,
                                                    const float* __restrict__ Km,
                                                    const float* __restrict__ Vm,
                                                    float* __restrict__ outp,
                                                    float* __restrict__ pl) {
    __shared__ float KVb[136 * 65];
    __shared__ float Qs[8 * 65];
    __shared__ float pb[8][132];

    const int b = blockIdx.z, hl = blockIdx.y, q0 = blockIdx.x * 8;
    const int h = HG + hl;
    const size_t bh = (size_t)(b * H_ + h);
    const int base = q0 - W_;
    const int tid = threadIdx.x, w = tid >> 5, lane = tid & 31;

    // Q tile
    for (int c = tid; c < 8 * 16; c += 256) {
        int r = c >> 4, d4 = (c & 15) << 2;
        float4 v = *(const float4*)(Qm + (bh * N_ + q0 + r) * D_ + d4);
        float* dst = Qs + r * 65 + d4;
        dst[0] = v.x; dst[1] = v.y; dst[2] = v.z; dst[3] = v.w;
    }
    // K band tile
    const float* Kp = Km + bh * N_ * D_;
    for (int c = tid; c < 136 * 16; c += 256) {
        int r = c >> 4, d4 = (c & 15) << 2;
        int k = base + r;
        float4 v = make_float4(0.f, 0.f, 0.f, 0.f);
        if (k >= 0 && k < N_) v = *(const float4*)(Kp + (size_t)k * D_ + d4);
        float* dst = KVb + r * 65 + d4;
        dst[0] = v.x; dst[1] = v.y; dst[2] = v.z; dst[3] = v.w;
    }
    __syncthreads();

    const int q = q0 + w;
    float sv[5];
#pragma unroll
    for (int j = 0; j < 5; j++) {
        int off = lane + 32 * j;
        if (off <= 2 * W_) {
            int k = base + w + off;
            bool ok = (k >= 0 && k < N_) && (d_mask[b * N_ + k] != 0);
            if (ok) {
                float acc = 0.0f;
                const float* qr = Qs + w * 65;
                const float* kr = KVb + (w + off) * 65;
#pragma unroll 8
                for (int d = 0; d < D_; d++) acc += qr[d] * kr[d];
                sv[j] = acc * SCALE;
            } else {
                sv[j] = NEGV;
            }
        } else {
            sv[j] = -3.0e38f;
        }
    }
    float mx = sv[0];
#pragma unroll
    for (int j = 1; j < 5; j++) mx = fmaxf(mx, sv[j]);
#pragma unroll
    for (int o = 16; o >= 1; o >>= 1)
        mx = fmaxf(mx, __shfl_xor_sync(0xffffffffu, mx, o));
    float es[5];
    float sum = 0.0f;
#pragma unroll
    for (int j = 0; j < 5; j++) { es[j] = __expf(sv[j] - mx); sum += es[j]; }
#pragma unroll
    for (int o = 16; o >= 1; o >>= 1)
        sum += __shfl_xor_sync(0xffffffffu, sum, o);
    float inv = 1.0f / sum;
#pragma unroll
    for (int j = 0; j < 5; j++) {
        int off = lane + 32 * j;
        if (off <= 2 * W_) pb[w][off] = es[j] * inv;
    }
    __syncwarp();

    // write full p_l row (band + zeros), coalesced float4
    const size_t prow = ((size_t)(b * HL + hl) * N_ + q) * N_;
    for (int c = lane; c < N_ / 4; c += 32) {
        int col0 = c * 4;
        float4 v;
        float* vp = &v.x;
#pragma unroll
        for (int t = 0; t < 4; t++) {
            int off = col0 + t - q + W_;
            vp[t] = (off >= 0 && off <= 2 * W_) ? pb[w][off] : 0.0f;
        }
        *(float4*)(&pl[prow + col0]) = v;
    }
    __syncthreads();

    // V band tile (reuse buffer)
    const float* Vp = Vm + bh * N_ * D_;
    for (int c = tid; c < 136 * 16; c += 256) {
        int r = c >> 4, d4 = (c & 15) << 2;
        int k = base + r;
        float4 v = make_float4(0.f, 0.f, 0.f, 0.f);
        if (k >= 0 && k < N_) v = *(const float4*)(Vp + (size_t)k * D_ + d4);
        float* dst = KVb + r * 65 + d4;
        dst[0] = v.x; dst[1] = v.y; dst[2] = v.z; dst[3] = v.w;
    }
    __syncthreads();

    float o0 = 0.0f, o1 = 0.0f;
#pragma unroll 4
    for (int off = 0; off <= 2 * W_; off++) {
        float pv = pb[w][off];
        const float* vr = KVb + (w + off) * 65;
        o0 += pv * vr[lane];
        o1 += pv * vr[32 + lane];
    }
    const size_t obase = (bh * N_ + q) * D_;
    outp[obase + lane] = o0;
    outp[obase + 32 + lane] = o1;
}

// ---------------------------------------------------------------------------
extern "C" void kernel_launch(void* const* d_in, const int* in_sizes, int n_in,
                              void* d_out, int out_size) {
    const float* Q = (const float*)d_in[0];
    const float* K = (const float*)d_in[1];
    const float* V = (const float*)d_in[2];
    const void* mask = d_in[3];

    float* out = (float*)d_out;
    float* pg = out + (size_t)B_ * H_ * N_ * D_;
    float* pl = pg + (size_t)B_ * HG * N_ * N_;

    prep_mask_kernel<<<1, 256>>>(mask);

    dim3 g1(N_ / 64, HG, B_);
    gpass1_kernel<<<g1, 256>>>(Q, K);
    gpass2_kernel<<<g1, 256>>>(V, out, pg);

    dim3 g2(N_ / 8, HL, B_);
    local_kernel<<<g2, 256>>>(Q, K, V, out, pl);
}

// round 2
// speedup vs baseline: 1.0003x; 1.0003x over previous
#include <cuda_runtime.h>

#define B_ 2
#define H_ 16
#define N_ 2048
#define D_ 64
#define HG 8
#define HL 8
#define W_ 64
#define SCALE 0.125f
#define NEGV (-1e12f)

// Scratch (allocation-free rule: __device__ globals)
__device__ float d_scores[(size_t)B_ * HG * N_ * N_];   // 256 MB: masked+scaled scores for global heads
__device__ float d_m[B_ * HG * N_];
__device__ float d_l[B_ * HG * N_];
__device__ int   d_mask[B_ * N_];

// ---------------------------------------------------------------------------
// Mask canonicalization: detect storage dtype (int32 / float32 / uint8) by
// pattern, convert to int 0/1. Deterministic for fixed bench inputs.
// ---------------------------------------------------------------------------
__global__ void prep_mask_kernel(const void* __restrict__ mraw) {
    __shared__ int mode;
    if (threadIdx.x == 0) {
        const unsigned int* w = (const unsigned int*)mraw;
        bool is_int = true, is_float = true;
        for (int i = 0; i < 64; i++) {
            unsigned int v = w[i];
            if (v > 1u) is_int = false;
            if (v != 0u && v != 0x3F800000u) is_float = false;
        }
        mode = is_int ? 1 : (is_float ? 2 : 0);
    }
    __syncthreads();
    int m = mode;
    for (int i = threadIdx.x; i < B_ * N_; i += blockDim.x) {
        int val;
        if (m == 1)      val = (((const int*)mraw)[i] != 0);
        else if (m == 2) val = (((const float*)mraw)[i] != 0.0f);
        else             val = (((const unsigned char*)mraw)[i] != 0);
        d_mask[i] = val;
    }
}

// ---------------------------------------------------------------------------
// Global heads pass 1: S = scale * Q K^T (masked -> NEGV), online (m, l),
// spill S to scratch. Block = 256 threads = 16x16 grid, 4x4 microtile,
// tile = 64 q rows x 64 k cols, loop over 32 k-tiles.
// Smem tiles padded to stride 65 -> conflict-free scalar LDS in microkernel.
// ---------------------------------------------------------------------------
__global__ void __launch_bounds__(256) gpass1_kernel(const float* __restrict__ Qm,
                                                     const float* __restrict__ Km) {
    __shared__ float Qs[64 * 65];
    __shared__ float Ks[64 * 65];
    const int b = blockIdx.z, h = blockIdx.y, q0 = blockIdx.x * 64;
    const float* Qp = Qm + ((size_t)(b * H_ + h) * N_ + q0) * D_;
    const float* Kp = Km + (size_t)(b * H_ + h) * N_ * D_;
    const int tid = threadIdx.x;
    const int ty = tid >> 4, tx = tid & 15;

    for (int c = tid; c < 64 * 16; c += 256) {
        int r = c >> 4, d4 = (c & 15) << 2;
        float4 v = *(const float4*)(Qp + r * D_ + d4);
        float* dst = Qs + r * 65 + d4;
        dst[0] = v.x; dst[1] = v.y; dst[2] = v.z; dst[3] = v.w;
    }

    float m[4], l[4];
#pragma unroll
    for (int i = 0; i < 4; i++) { m[i] = NEGV; l[i] = 0.0f; }

    const int mrow = b * N_;
    const size_t srow0 = ((size_t)(b * HG + h) * N_ + q0) * N_;

    for (int kt = 0; kt < N_ / 64; kt++) {
        __syncthreads();
        const float* Kt = Kp + (size_t)kt * 64 * D_;
        for (int c = tid; c < 64 * 16; c += 256) {
            int r = c >> 4, d4 = (c & 15) << 2;
            float4 v = *(const float4*)(Kt + r * D_ + d4);
            float* dst = Ks + r * 65 + d4;
            dst[0] = v.x; dst[1] = v.y; dst[2] = v.z; dst[3] = v.w;
        }
        __syncthreads();

        float s[4][4];
#pragma unroll
        for (int i = 0; i < 4; i++)
#pragma unroll
            for (int j = 0; j < 4; j++) s[i][j] = 0.0f;

#pragma unroll 8
        for (int d = 0; d < 64; d++) {
            float qv[4], kv[4];
#pragma unroll
            for (int i = 0; i < 4; i++) qv[i] = Qs[(ty * 4 + i) * 65 + d];
#pragma unroll
            for (int j = 0; j < 4; j++) kv[j] = Ks[(tx * 4 + j) * 65 + d];
#pragma unroll
            for (int i = 0; i < 4; i++)
#pragma unroll
                for (int j = 0; j < 4; j++) s[i][j] += qv[i] * kv[j];
        }

        // scale + mask
        const int kbase = kt * 64 + tx * 4;
#pragma unroll
        for (int j = 0; j < 4; j++) {
            bool mk = (d_mask[mrow + kbase + j] != 0);
#pragma unroll
            for (int i = 0; i < 4; i++)
                s[i][j] = mk ? s[i][j] * SCALE : NEGV;
        }

        // online softmax stats per row (16-lane groups = same ty)
#pragma unroll
        for (int i = 0; i < 4; i++) {
            float tmax = fmaxf(fmaxf(s[i][0], s[i][1]), fmaxf(s[i][2], s[i][3]));
#pragma unroll
            for (int o = 8; o >= 1; o >>= 1)
                tmax = fmaxf(tmax, __shfl_xor_sync(0xffffffffu, tmax, o));
            float nm = fmaxf(m[i], tmax);
            float es = __expf(s[i][0] - nm) + __expf(s[i][1] - nm) +
                       __expf(s[i][2] - nm) + __expf(s[i][3] - nm);
#pragma unroll
            for (int o = 8; o >= 1; o >>= 1)
                es += __shfl_xor_sync(0xffffffffu, es, o);
            l[i] = l[i] * __expf(m[i] - nm) + es;
            m[i] = nm;
            float4 sv = make_float4(s[i][0], s[i][1], s[i][2], s[i][3]);
            *(float4*)(&d_scores[srow0 + (size_t)(ty * 4 + i) * N_ + kbase]) = sv;
        }
    }

    if (tx == 0) {
#pragma unroll
        for (int i = 0; i < 4; i++) {
            int rid = (b * HG + h) * N_ + q0 + ty * 4 + i;
            d_m[rid] = m[i];
            d_l[rid] = l[i];
        }
    }
}

// ---------------------------------------------------------------------------
// Global heads pass 2: p = exp(s - m)/l (write p_g), out = p @ V.
// Same 16x16 / 4x4 microtile structure; P staged transposed in smem for PV.
// ---------------------------------------------------------------------------
__global__ void __launch_bounds__(256) gpass2_kernel(const float* __restrict__ Vm,
                                                     float* __restrict__ outp,
                                                     float* __restrict__ pg) {
    __shared__ float Vs[64 * 65];        // [k][d]
    __shared__ float Ps[64 * 65];        // [k][q]
    const int b = blockIdx.z, h = blockIdx.y, q0 = blockIdx.x * 64;
    const float* Vp = Vm + (size_t)(b * H_ + h) * N_ * D_;
    const int tid = threadIdx.x;
    const int ty = tid >> 4, tx = tid & 15;

    float m[4], invl[4];
#pragma unroll
    for (int i = 0; i < 4; i++) {
        int rid = (b * HG + h) * N_ + q0 + ty * 4 + i;
        m[i] = d_m[rid];
        invl[i] = 1.0f / d_l[rid];
    }

    float o[4][4];
#pragma unroll
    for (int i = 0; i < 4; i++)
#pragma unroll
        for (int j = 0; j < 4; j++) o[i][j] = 0.0f;

    const size_t srow0 = ((size_t)(b * HG + h) * N_ + q0) * N_;

    for (int kt = 0; kt < N_ / 64; kt++) {
        __syncthreads();
        const float* Vt = Vp + (size_t)kt * 64 * D_;
        for (int c = tid; c < 64 * 16; c += 256) {
            int r = c >> 4, d4 = (c & 15) << 2;
            float4 v = *(const float4*)(Vt + r * D_ + d4);
            float* dst = Vs + r * 65 + d4;
            dst[0] = v.x; dst[1] = v.y; dst[2] = v.z; dst[3] = v.w;
        }
        const int kbase = kt * 64 + tx * 4;
#pragma unroll
        for (int i = 0; i < 4; i++) {
            size_t idx = srow0 + (size_t)(ty * 4 + i) * N_ + kbase;
            float4 sv = *(const float4*)(&d_scores[idx]);
            float4 pv;
            pv.x = __expf(sv.x - m[i]) * invl[i];
            pv.y = __expf(sv.y - m[i]) * invl[i];
            pv.z = __expf(sv.z - m[i]) * invl[i];
            pv.w = __expf(sv.w - m[i]) * invl[i];
            *(float4*)(&pg[idx]) = pv;
            Ps[(tx * 4 + 0) * 65 + ty * 4 + i] = pv.x;
            Ps[(tx * 4 + 1) * 65 + ty * 4 + i] = pv.y;
            Ps[(tx * 4 + 2) * 65 + ty * 4 + i] = pv.z;
            Ps[(tx * 4 + 3) * 65 + ty * 4 + i] = pv.w;
        }
        __syncthreads();

#pragma unroll 8
        for (int k = 0; k < 64; k++) {
            float pv[4], vv[4];
#pragma unroll
            for (int i = 0; i < 4; i++) pv[i] = Ps[k * 65 + ty * 4 + i];
#pragma unroll
            for (int j = 0; j < 4; j++) vv[j] = Vs[k * 65 + tx * 4 + j];
#pragma unroll
            for (int i = 0; i < 4; i++)
#pragma unroll
                for (int j = 0; j < 4; j++) o[i][j] += pv[i] * vv[j];
        }
    }

#pragma unroll
    for (int i = 0; i < 4; i++) {
        float4 ov = make_float4(o[i][0], o[i][1], o[i][2], o[i][3]);
        *(float4*)(&outp[((size_t)(b * H_ + h) * N_ + q0 + ty * 4 + i) * D_ + tx * 4]) = ov;
    }
}

// ---------------------------------------------------------------------------
// Local (banded) heads: one warp per q row, 8 rows per block.
// Band tile (136 keys) staged in one smem buffer, K phase then V phase.
// Full p_l rows written (band values + zeros) -> fused zero-fill.
// ---------------------------------------------------------------------------
__global__ void __launch_bounds__(256) local_kernel(const float* __restrict__ Qm,
                                                    const float* __restrict__ Km,
                                                    const float* __restrict__ Vm,
                                                    float* __restrict__ outp,
                                                    float* __restrict__ pl) {
    __shared__ float KVb[136 * 65];
    __shared__ float Qs[8 * 65];
    __shared__ float pb[8][132];

    const int b = blockIdx.z, hl = blockIdx.y, q0 = blockIdx.x * 8;
    const int h = HG + hl;
    const size_t bh = (size_t)(b * H_ + h);
    const int base = q0 - W_;
    const int tid = threadIdx.x, w = tid >> 5, lane = tid & 31;

    // Q tile
    for (int c = tid; c < 8 * 16; c += 256) {
        int r = c >> 4, d4 = (c & 15) << 2;
        float4 v = *(const float4*)(Qm + (bh * N_ + q0 + r) * D_ + d4);
        float* dst = Qs + r * 65 + d4;
        dst[0] = v.x; dst[1] = v.y; dst[2] = v.z; dst[3] = v.w;
    }
    // K band tile
    const float* Kp = Km + bh * N_ * D_;
    for (int c = tid; c < 136 * 16; c += 256) {
        int r = c >> 4, d4 = (c & 15) << 2;
        int k = base + r;
        float4 v = make_float4(0.f, 0.f, 0.f, 0.f);
        if (k >= 0 && k < N_) v = *(const float4*)(Kp + (size_t)k * D_ + d4);
        float* dst = KVb + r * 65 + d4;
        dst[0] = v.x; dst[1] = v.y; dst[2] = v.z; dst[3] = v.w;
    }
    __syncthreads();

    const int q = q0 + w;
    float sv[5];
#pragma unroll
    for (int j = 0; j < 5; j++) {
        int off = lane + 32 * j;
        if (off <= 2 * W_) {
            int k = base + w + off;
            bool ok = (k >= 0 && k < N_) && (d_mask[b * N_ + k] != 0);
            if (ok) {
                float acc = 0.0f;
                const float* qr = Qs + w * 65;
                const float* kr = KVb + (w + off) * 65;
#pragma unroll 8
                for (int d = 0; d < D_; d++) acc += qr[d] * kr[d];
                sv[j] = acc * SCALE;
            } else {
                sv[j] = NEGV;
            }
        } else {
            sv[j] = -3.0e38f;
        }
    }
    float mx = sv[0];
#pragma unroll
    for (int j = 1; j < 5; j++) mx = fmaxf(mx, sv[j]);
#pragma unroll
    for (int o = 16; o >= 1; o >>= 1)
        mx = fmaxf(mx, __shfl_xor_sync(0xffffffffu, mx, o));
    float es[5];
    float sum = 0.0f;
#pragma unroll
    for (int j = 0; j < 5; j++) { es[j] = __expf(sv[j] - mx); sum += es[j]; }
#pragma unroll
    for (int o = 16; o >= 1; o >>= 1)
        sum += __shfl_xor_sync(0xffffffffu, sum, o);
    float inv = 1.0f / sum;
#pragma unroll
    for (int j = 0; j < 5; j++) {
        int off = lane + 32 * j;
        if (off <= 2 * W_) pb[w][off] = es[j] * inv;
    }
    __syncwarp();

    // write full p_l row (band + zeros), coalesced float4
    const size_t prow = ((size_t)(b * HL + hl) * N_ + q) * N_;
    for (int c = lane; c < N_ / 4; c += 32) {
        int col0 = c * 4;
        float4 v;
        float* vp = &v.x;
#pragma unroll
        for (int t = 0; t < 4; t++) {
            int off = col0 + t - q + W_;
            vp[t] = (off >= 0 && off <= 2 * W_) ? pb[w][off] : 0.0f;
        }
        *(float4*)(&pl[prow + col0]) = v;
    }
    __syncthreads();

    // V band tile (reuse buffer)
    const float* Vp = Vm + bh * N_ * D_;
    for (int c = tid; c < 136 * 16; c += 256) {
        int r = c >> 4, d4 = (c & 15) << 2;
        int k = base + r;
        float4 v = make_float4(0.f, 0.f, 0.f, 0.f);
        if (k >= 0 && k < N_) v = *(const float4*)(Vp + (size_t)k * D_ + d4);
        float* dst = KVb + r * 65 + d4;
        dst[0] = v.x; dst[1] = v.y; dst[2] = v.z; dst[3] = v.w;
    }
    __syncthreads();

    float o0 = 0.0f, o1 = 0.0f;
#pragma unroll 4
    for (int off = 0; off <= 2 * W_; off++) {
        float pv = pb[w][off];
        const float* vr = KVb + (w + off) * 65;
        o0 += pv * vr[lane];
        o1 += pv * vr[32 + lane];
    }
    const size_t obase = (bh * N_ + q) * D_;
    outp[obase + lane] = o0;
    outp[obase + 32 + lane] = o1;
}

// ---------------------------------------------------------------------------
extern "C" void kernel_launch(void* const* d_in, const int* in_sizes, int n_in,
                              void* d_out, int out_size) {
    const float* Q = (const float*)d_in[0];
    const float* K = (const float*)d_in[1];
    const float* V = (const float*)d_in[2];
    const void* mask = d_in[3];

    float* out = (float*)d_out;
    float* pg = out + (size_t)B_ * H_ * N_ * D_;
    float* pl = pg + (size_t)B_ * HG * N_ * N_;

    prep_mask_kernel<<<1, 256>>>(mask);

    dim3 g1(N_ / 64, HG, B_);
    gpass1_kernel<<<g1, 256>>>(Q, K);
    gpass2_kernel<<<g1, 256>>>(V, out, pg);

    dim3 g2(N_ / 8, HL, B_);
    local_kernel<<<g2, 256>>>(Q, K, V, out, pl);
}

// round 4
// speedup vs baseline: 1.0797x; 1.0794x over previous
#include <cuda_runtime.h>
#include <cuda_bf16.h>
#include <mma.h>
#include <stdint.h>

using namespace nvcuda;

#define B_ 2
#define H_ 16
#define N_ 2048
#define D_ 64
#define HG 8
#define HL 8
#define W_ 64
#define SCALE 0.125f
#define NEGV (-1e12f)

// byte offsets in dynamic smem
#define OQH 0u
#define OQL 18432u
#define OKH 36864u
#define OKL 55296u
#define OVH 73728u
#define OVL 92160u
#define OS  110592u     /* per-warp 8704B: S f32 [16][136] / P hi+lo bf16 [16][136]x2 */
#define OMF 180224u     /* float2[2048] */
#define OLR 196608u     /* float[128] */
#define SMEM_SZ 197120

__device__ int d_mask[B_ * N_];

typedef wmma::fragment<wmma::matrix_a, 16, 16, 16, __nv_bfloat16, wmma::row_major> FragA;
typedef wmma::fragment<wmma::matrix_b, 16, 16, 16, __nv_bfloat16, wmma::col_major> FragBc;
typedef wmma::fragment<wmma::matrix_b, 16, 16, 16, __nv_bfloat16, wmma::row_major> FragBr;
typedef wmma::fragment<wmma::accumulator, 16, 16, 16, float> FragC;

__global__ void prep_mask_kernel(const void* __restrict__ mraw) {
    __shared__ int mode;
    if (threadIdx.x == 0) {
        const unsigned int* w = (const unsigned int*)mraw;
        bool ii = true, ff = true;
        for (int i = 0; i < 64; i++) {
            unsigned int v = w[i];
            if (v > 1u) ii = false;
            if (v != 0u && v != 0x3F800000u) ff = false;
        }
        mode = ii ? 1 : (ff ? 2 : 0);
    }
    __syncthreads();
    int m = mode;
    for (int i = threadIdx.x; i < B_ * N_; i += blockDim.x) {
        int v;
        if (m == 1)      v = (((const int*)mraw)[i] != 0);
        else if (m == 2) v = (((const float*)mraw)[i] != 0.0f);
        else             v = (((const unsigned char*)mraw)[i] != 0);
        d_mask[i] = v;
    }
}

__device__ __forceinline__ void split2(float a, float b, uint32_t& hw, uint32_t& lw) {
    __nv_bfloat16 ha = __float2bfloat16(a);
    float fa = __uint_as_float((uint32_t)__bfloat16_as_ushort(ha) << 16);
    __nv_bfloat16 la = __float2bfloat16(a - fa);
    __nv_bfloat16 hb = __float2bfloat16(b);
    float fb = __uint_as_float((uint32_t)__bfloat16_as_ushort(hb) << 16);
    __nv_bfloat16 lb = __float2bfloat16(b - fb);
    hw = (uint32_t)__bfloat16_as_ushort(ha) | ((uint32_t)__bfloat16_as_ushort(hb) << 16);
    lw = (uint32_t)__bfloat16_as_ushort(la) | ((uint32_t)__bfloat16_as_ushort(lb) << 16);
}

// fp32 [128][64] row-major -> bf16 hi/lo smem tiles stride 72
__device__ __forceinline__ void loadsplit(const float* __restrict__ src,
                                          __nv_bfloat16* H, __nv_bfloat16* L, int tid) {
    for (int idx = tid; idx < 2048; idx += 256) {
        int r = idx >> 4, c4 = (idx & 15) << 2;
        float4 v = *(const float4*)(src + r * D_ + c4);
        uint32_t h01, l01, h23, l23;
        split2(v.x, v.y, h01, l01);
        split2(v.z, v.w, h23, l23);
        uint32_t* hp = (uint32_t*)(H + r * 72 + c4);
        uint32_t* lp = (uint32_t*)(L + r * 72 + c4);
        hp[0] = h01; hp[1] = h23;
        lp[0] = l01; lp[1] = l23;
    }
}

// QK: S[16][128] for this warp -> Sw (f32, ld 136)
__device__ __forceinline__ void qk_store(const __nv_bfloat16* QH, const __nv_bfloat16* QL,
                                         const __nv_bfloat16* KH, const __nv_bfloat16* KL,
                                         float* Sw, int w) {
    const __nv_bfloat16* qh = QH + w * 16 * 72;
    const __nv_bfloat16* ql = QL + w * 16 * 72;
#pragma unroll
    for (int nt = 0; nt < 8; nt++) {
        FragC c;
        wmma::fill_fragment(c, 0.0f);
#pragma unroll
        for (int kk = 0; kk < 4; kk++) {
            FragA aH, aL;
            FragBc bH, bL;
            wmma::load_matrix_sync(aH, qh + kk * 16, 72);
            wmma::load_matrix_sync(aL, ql + kk * 16, 72);
            wmma::load_matrix_sync(bH, KH + nt * 16 * 72 + kk * 16, 72);
            wmma::load_matrix_sync(bL, KL + nt * 16 * 72 + kk * 16, 72);
            wmma::mma_sync(c, aH, bH, c);
            wmma::mma_sync(c, aH, bL, c);
            wmma::mma_sync(c, aL, bH, c);
        }
        wmma::store_matrix_sync(Sw + nt * 16, c, 136, wmma::mem_row_major);
    }
}

// ---------------------------------------------------------------------------
// Global heads: fused wmma kernel. CTA = 128 q rows of one (b,h).
// ---------------------------------------------------------------------------
__global__ void __launch_bounds__(256, 1)
gattn_kernel(const float* __restrict__ Q, const float* __restrict__ K,
             const float* __restrict__ V, float* __restrict__ outp,
             float* __restrict__ pg) {
    extern __shared__ char sm[];
    __nv_bfloat16* QH = (__nv_bfloat16*)(sm + OQH);
    __nv_bfloat16* QL = (__nv_bfloat16*)(sm + OQL);
    __nv_bfloat16* KH = (__nv_bfloat16*)(sm + OKH);
    __nv_bfloat16* KL = (__nv_bfloat16*)(sm + OKL);
    __nv_bfloat16* VH = (__nv_bfloat16*)(sm + OVH);
    __nv_bfloat16* VL = (__nv_bfloat16*)(sm + OVL);
    float2* mf = (float2*)(sm + OMF);
    float* Lrow = (float*)(sm + OLR);

    const int b = blockIdx.z, h = blockIdx.y, q0 = blockIdx.x * 128;
    const int tid = threadIdx.x, w = tid >> 5, lane = tid & 31;
    float* Sw = (float*)(sm + OS + (uint32_t)w * 8704u);
    __nv_bfloat16* PHw = (__nv_bfloat16*)Sw;
    __nv_bfloat16* PLw = PHw + 16 * 136;

    const float* Qp = Q + ((size_t)(b * H_ + h) * N_ + q0) * D_;
    const float* Kp = K + (size_t)(b * H_ + h) * N_ * D_;
    const float* Vp = V + (size_t)(b * H_ + h) * N_ * D_;

    for (int i = tid; i < N_; i += 256)
        mf[i] = d_mask[b * N_ + i] ? make_float2(SCALE, 0.0f) : make_float2(0.0f, NEGV);
    loadsplit(Qp, QH, QL, tid);

    const int r = lane >> 1;
    const int c0 = (lane & 1) * 64;

    // ---------- pass 1: row sums ----------
    float lp = 0.0f;
    for (int kt = 0; kt < 16; kt++) {
        __syncthreads();
        loadsplit(Kp + (size_t)kt * 128 * D_, KH, KL, tid);
        __syncthreads();
        qk_store(QH, QL, KH, KL, Sw, w);
        __syncwarp();
        const float* srow = Sw + r * 136 + c0;
        const float2* mrow = mf + kt * 128 + c0;
#pragma unroll 8
        for (int j = 0; j < 64; j++)
            lp += __expf(fmaf(srow[j], mrow[j].x, mrow[j].y));
    }
    lp += __shfl_xor_sync(0xffffffffu, lp, 1);
    if ((lane & 1) == 0) Lrow[w * 16 + r] = lp;
    __syncthreads();
    const float invl = 1.0f / Lrow[w * 16 + r];

    // ---------- pass 2: recompute QK -> p_g + PV ----------
    FragC Of[4];
#pragma unroll
    for (int nt = 0; nt < 4; nt++) wmma::fill_fragment(Of[nt], 0.0f);

    for (int kt = 0; kt < 16; kt++) {
        __syncthreads();
        loadsplit(Kp + (size_t)kt * 128 * D_, KH, KL, tid);
        loadsplit(Vp + (size_t)kt * 128 * D_, VH, VL, tid);
        __syncthreads();
        qk_store(QH, QL, KH, KL, Sw, w);
        __syncwarp();

        // p row chunk: compute, write pg fp32, buffer hi/lo packs
        uint32_t ph[32], plo[32];
        {
            const float* srow = Sw + r * 136 + c0;
            const float2* mrow = mf + kt * 128 + c0;
            float4* pgrow = (float4*)(pg + ((size_t)(b * HG + h) * N_ + q0 + w * 16 + r) * N_ +
                                      kt * 128 + c0);
#pragma unroll
            for (int j0 = 0; j0 < 64; j0 += 4) {
                float p0 = __expf(fmaf(srow[j0 + 0], mrow[j0 + 0].x, mrow[j0 + 0].y)) * invl;
                float p1 = __expf(fmaf(srow[j0 + 1], mrow[j0 + 1].x, mrow[j0 + 1].y)) * invl;
                float p2 = __expf(fmaf(srow[j0 + 2], mrow[j0 + 2].x, mrow[j0 + 2].y)) * invl;
                float p3 = __expf(fmaf(srow[j0 + 3], mrow[j0 + 3].x, mrow[j0 + 3].y)) * invl;
                pgrow[j0 >> 2] = make_float4(p0, p1, p2, p3);
                split2(p0, p1, ph[(j0 >> 1)], plo[(j0 >> 1)]);
                split2(p2, p3, ph[(j0 >> 1) + 1], plo[(j0 >> 1) + 1]);
            }
        }
        __syncwarp();   // all lanes done READING S before overwrite with P
#pragma unroll
        for (int jj = 0; jj < 32; jj++) {
            *(uint32_t*)(PHw + r * 136 + c0 + jj * 2) = ph[jj];
            *(uint32_t*)(PLw + r * 136 + c0 + jj * 2) = plo[jj];
        }
        __syncwarp();

        // PV: O[16][64] += P[16][128] @ V[128][64]
#pragma unroll
        for (int nt = 0; nt < 4; nt++) {
#pragma unroll
            for (int kk = 0; kk < 8; kk++) {
                FragA aH, aL;
                FragBr bH, bL;
                wmma::load_matrix_sync(aH, PHw + kk * 16, 136);
                wmma::load_matrix_sync(aL, PLw + kk * 16, 136);
                wmma::load_matrix_sync(bH, VH + kk * 16 * 72 + nt * 16, 72);
                wmma::load_matrix_sync(bL, VL + kk * 16 * 72 + nt * 16, 72);
                wmma::mma_sync(Of[nt], aH, bH, Of[nt]);
                wmma::mma_sync(Of[nt], aH, bL, Of[nt]);
                wmma::mma_sync(Of[nt], aL, bH, Of[nt]);
            }
        }
    }

    // epilogue: store O directly to gmem (row-major, ld = 64)
    float* ob = outp + ((size_t)(b * H_ + h) * N_ + q0 + w * 16) * D_;
#pragma unroll
    for (int nt = 0; nt < 4; nt++)
        wmma::store_matrix_sync(ob + nt * 16, Of[nt], 64, wmma::mem_row_major);
}

// ---------------------------------------------------------------------------
// Local (banded) heads: warp = q row, d-outer QK with register acc[5].
// ---------------------------------------------------------------------------
__global__ void __launch_bounds__(256) local_kernel(const float* __restrict__ Qm,
                                                    const float* __restrict__ Km,
                                                    const float* __restrict__ Vm,
                                                    float* __restrict__ outp,
                                                    float* __restrict__ pl) {
    __shared__ float KVb[136 * 65];
    __shared__ float Qs[8 * 65];
    __shared__ float pb[8][132];

    const int b = blockIdx.z, hl = blockIdx.y, q0 = blockIdx.x * 8;
    const int h = HG + hl;
    const size_t bh = (size_t)(b * H_ + h);
    const int base = q0 - W_;
    const int tid = threadIdx.x, w = tid >> 5, lane = tid & 31;

    for (int c = tid; c < 8 * 16; c += 256) {
        int r = c >> 4, d4 = (c & 15) << 2;
        float4 v = *(const float4*)(Qm + (bh * N_ + q0 + r) * D_ + d4);
        float* dst = Qs + r * 65 + d4;
        dst[0] = v.x; dst[1] = v.y; dst[2] = v.z; dst[3] = v.w;
    }
    const float* Kp = Km + bh * N_ * D_;
    for (int c = tid; c < 136 * 16; c += 256) {
        int r = c >> 4, d4 = (c & 15) << 2;
        int k = base + r;
        float4 v = make_float4(0.f, 0.f, 0.f, 0.f);
        if (k >= 0 && k < N_) v = *(const float4*)(Kp + (size_t)k * D_ + d4);
        float* dst = KVb + r * 65 + d4;
        dst[0] = v.x; dst[1] = v.y; dst[2] = v.z; dst[3] = v.w;
    }
    __syncthreads();

    const int q = q0 + w;
    float acc[5] = {0.f, 0.f, 0.f, 0.f, 0.f};
    {
        const float* qr = Qs + w * 65;
        const float* kr = KVb + (w + lane) * 65;
#pragma unroll 4
        for (int d = 0; d < D_; d++) {
            float qd = qr[d];
#pragma unroll
            for (int j = 0; j < 4; j++)
                acc[j] += qd * kr[32 * j * 65 + d];
            if (lane == 0) acc[4] += qd * KVb[(w + 128) * 65 + d];
        }
    }
    float sv[5];
#pragma unroll
    for (int j = 0; j < 5; j++) {
        int off = lane + 32 * j;
        if (off <= 2 * W_) {
            int k = base + w + off;
            bool ok = (k >= 0 && k < N_) && (d_mask[b * N_ + k] != 0);
            sv[j] = ok ? acc[j] * SCALE : NEGV;
        } else sv[j] = -3.0e38f;
    }
    float mx = sv[0];
#pragma unroll
    for (int j = 1; j < 5; j++) mx = fmaxf(mx, sv[j]);
#pragma unroll
    for (int o = 16; o >= 1; o >>= 1) mx = fmaxf(mx, __shfl_xor_sync(0xffffffffu, mx, o));
    float es[5], sum = 0.0f;
#pragma unroll
    for (int j = 0; j < 5; j++) { es[j] = __expf(sv[j] - mx); sum += es[j]; }
#pragma unroll
    for (int o = 16; o >= 1; o >>= 1) sum += __shfl_xor_sync(0xffffffffu, sum, o);
    float inv = 1.0f / sum;
#pragma unroll
    for (int j = 0; j < 5; j++) {
        int off = lane + 32 * j;
        if (off <= 2 * W_) pb[w][off] = es[j] * inv;
    }
    __syncwarp();

    const size_t prow = ((size_t)(b * HL + hl) * N_ + q) * N_;
    for (int c = lane; c < N_ / 4; c += 32) {
        int col0 = c * 4;
        float4 v;
        float* vp = &v.x;
#pragma unroll
        for (int t = 0; t < 4; t++) {
            int off = col0 + t - q + W_;
            vp[t] = (off >= 0 && off <= 2 * W_) ? pb[w][off] : 0.0f;
        }
        *(float4*)(&pl[prow + col0]) = v;
    }
    __syncthreads();

    const float* Vp = Vm + bh * N_ * D_;
    for (int c = tid; c < 136 * 16; c += 256) {
        int r = c >> 4, d4 = (c & 15) << 2;
        int k = base + r;
        float4 v = make_float4(0.f, 0.f, 0.f, 0.f);
        if (k >= 0 && k < N_) v = *(const float4*)(Vp + (size_t)k * D_ + d4);
        float* dst = KVb + r * 65 + d4;
        dst[0] = v.x; dst[1] = v.y; dst[2] = v.z; dst[3] = v.w;
    }
    __syncthreads();

    float o0 = 0.0f, o1 = 0.0f;
#pragma unroll 4
    for (int off = 0; off <= 2 * W_; off++) {
        float pv = pb[w][off];
        const float* vr = KVb + (w + off) * 65;
        o0 += pv * vr[lane];
        o1 += pv * vr[32 + lane];
    }
    const size_t obase = (bh * N_ + q) * D_;
    outp[obase + lane] = o0;
    outp[obase + 32 + lane] = o1;
}

// ---------------------------------------------------------------------------
extern "C" void kernel_launch(void* const* d_in, const int* in_sizes, int n_in,
                              void* d_out, int out_size) {
    const float* Q = (const float*)d_in[0];
    const float* K = (const float*)d_in[1];
    const float* V = (const float*)d_in[2];
    const void* mask = d_in[3];

    float* out = (float*)d_out;
    float* pg = out + (size_t)B_ * H_ * N_ * D_;
    float* pl = pg + (size_t)B_ * HG * N_ * N_;

    static int attr_set = 0;
    if (!attr_set) {
        cudaFuncSetAttribute(gattn_kernel, cudaFuncAttributeMaxDynamicSharedMemorySize, SMEM_SZ);
        attr_set = 1;
    }

    prep_mask_kernel<<<1, 256>>>(mask);

    dim3 g1(N_ / 128, HG, B_);
    gattn_kernel<<<g1, 256, SMEM_SZ>>>(Q, K, V, out, pg);

    dim3 g2(N_ / 8, HL, B_);
    local_kernel<<<g2, 256>>>(Q, K, V, out, pl);
}

// round 5
// speedup vs baseline: 1.7841x; 1.6524x over previous
#include <cuda_runtime.h>
#include <cuda_bf16.h>
#include <stdint.h>

#define B_ 2
#define H_ 16
#define N_ 2048
#define D_ 64
#define HG 8
#define HL 8
#define W_ 64
#define SCALE 0.125f
#define NEGV (-1e12f)

__device__ int d_mask[B_ * N_];
__device__ unsigned int d_mb[B_ * N_ / 32];

// ---- smem layout (bytes) ----
#define OQH 0u
#define OQL 36864u
#define OKH 73728u
#define OKL 92160u
#define OVH 110592u
#define OVL 129024u
#define OMB 147456u
#define SMEM_SZ 147968

__device__ __forceinline__ uint32_t smem_u32(const void* p) {
    uint32_t a;
    asm("{ .reg .u64 t; cvta.to.shared.u64 t, %1; cvt.u32.u64 %0, t; }" : "=r"(a) : "l"(p));
    return a;
}
__device__ __forceinline__ void ldsm4(uint32_t a[4], uint32_t addr) {
    asm volatile("ldmatrix.sync.aligned.m8n8.x4.shared.b16 {%0,%1,%2,%3}, [%4];"
                 : "=r"(a[0]), "=r"(a[1]), "=r"(a[2]), "=r"(a[3]) : "r"(addr));
}
__device__ __forceinline__ void ldsm2(uint32_t b[2], uint32_t addr) {
    asm volatile("ldmatrix.sync.aligned.m8n8.x2.shared.b16 {%0,%1}, [%2];"
                 : "=r"(b[0]), "=r"(b[1]) : "r"(addr));
}
__device__ __forceinline__ void ldsm2t(uint32_t b[2], uint32_t addr) {
    asm volatile("ldmatrix.sync.aligned.m8n8.x2.trans.shared.b16 {%0,%1}, [%2];"
                 : "=r"(b[0]), "=r"(b[1]) : "r"(addr));
}
__device__ __forceinline__ void mma16816(float c[4], const uint32_t a[4], uint32_t b0, uint32_t b1) {
    asm volatile("mma.sync.aligned.m16n8k16.row.col.f32.bf16.bf16.f32 "
                 "{%0,%1,%2,%3}, {%4,%5,%6,%7}, {%8,%9}, {%0,%1,%2,%3};"
                 : "+f"(c[0]), "+f"(c[1]), "+f"(c[2]), "+f"(c[3])
                 : "r"(a[0]), "r"(a[1]), "r"(a[2]), "r"(a[3]), "r"(b0), "r"(b1));
}
__device__ __forceinline__ uint32_t pack2(float lo, float hi) {
    __nv_bfloat162 t = __floats2bfloat162_rn(lo, hi);
    return *(uint32_t*)&t;
}
__device__ __forceinline__ float bhi(float x) {
    return __bfloat162float(__float2bfloat16(x));
}
__device__ __forceinline__ void split2(float a, float b, uint32_t& hw, uint32_t& lw) {
    __nv_bfloat16 ha = __float2bfloat16(a);
    float fa = __bfloat162float(ha);
    __nv_bfloat16 hb = __float2bfloat16(b);
    float fb = __bfloat162float(hb);
    hw = (uint32_t)__bfloat16_as_ushort(ha) | ((uint32_t)__bfloat16_as_ushort(hb) << 16);
    lw = (uint32_t)__bfloat16_as_ushort(__float2bfloat16(a - fa)) |
         ((uint32_t)__bfloat16_as_ushort(__float2bfloat16(b - fb)) << 16);
}

__global__ void prep_mask_kernel(const void* __restrict__ mraw) {
    __shared__ int mode;
    if (threadIdx.x == 0) {
        const unsigned int* w = (const unsigned int*)mraw;
        bool ii = true, ff = true;
        for (int i = 0; i < 64; i++) {
            unsigned int v = w[i];
            if (v > 1u) ii = false;
            if (v != 0u && v != 0x3F800000u) ff = false;
        }
        mode = ii ? 1 : (ff ? 2 : 0);
    }
    __syncthreads();
    int m = mode;
    for (int i = threadIdx.x; i < B_ * N_; i += blockDim.x) {
        int v;
        if (m == 1)      v = (((const int*)mraw)[i] != 0);
        else if (m == 2) v = (((const float*)mraw)[i] != 0.0f);
        else             v = (((const unsigned char*)mraw)[i] != 0);
        d_mask[i] = v;
    }
    __syncthreads();
    for (int i = threadIdx.x; i < B_ * N_ / 32; i += blockDim.x) {
        unsigned int w = 0;
        for (int k = 0; k < 32; k++)
            if (d_mask[i * 32 + k]) w |= 1u << k;
        d_mb[i] = w;
    }
}

// fp32 [rows][64] -> bf16 hi/lo smem (stride 72 elems)
__device__ __forceinline__ void loadsplit(const float* __restrict__ src,
                                          __nv_bfloat16* H, __nv_bfloat16* L,
                                          int tid, int n16) {
    for (int idx = tid; idx < n16; idx += 512) {
        int r = idx >> 4, c4 = (idx & 15) << 2;
        float4 v = *(const float4*)(src + r * D_ + c4);
        uint32_t h01, l01, h23, l23;
        split2(v.x, v.y, h01, l01);
        split2(v.z, v.w, h23, l23);
        uint32_t* hp = (uint32_t*)(H + r * 72 + c4);
        uint32_t* lp = (uint32_t*)(L + r * 72 + c4);
        hp[0] = h01; hp[1] = h23;
        lp[0] = l01; lp[1] = l23;
    }
}

// ---------------------------------------------------------------------------
// Global heads: register-resident flash. CTA = 256 q rows of one (b,h).
// 512 threads, 16 warps; warp = 16 q-rows x all 128 keys of each kt tile.
// ---------------------------------------------------------------------------
__global__ void __launch_bounds__(512, 1)
gattn_kernel(const float* __restrict__ Q, const float* __restrict__ K,
             const float* __restrict__ V, float* __restrict__ outp,
             float* __restrict__ pg) {
    extern __shared__ char sm[];
    __nv_bfloat16* QH = (__nv_bfloat16*)(sm + OQH);
    __nv_bfloat16* QL = (__nv_bfloat16*)(sm + OQL);
    __nv_bfloat16* KHp = (__nv_bfloat16*)(sm + OKH);
    __nv_bfloat16* KLp = (__nv_bfloat16*)(sm + OKL);
    __nv_bfloat16* VHp = (__nv_bfloat16*)(sm + OVH);
    __nv_bfloat16* VLp = (__nv_bfloat16*)(sm + OVL);
    unsigned int* mbS = (unsigned int*)(sm + OMB);

    const int b = blockIdx.z, h = blockIdx.y, q0 = blockIdx.x * 256;
    const int tid = threadIdx.x, wq = tid >> 5, lane = tid & 31;
    const int q0w = wq * 16;
    const int l7 = lane & 7, l8 = lane & 8, l15 = lane & 15;
    const int lq = lane >> 2, lc = lane & 3;

    const float* Qp = Q + ((size_t)(b * H_ + h) * N_ + q0) * D_;
    const float* Kp = K + (size_t)(b * H_ + h) * N_ * D_;
    const float* Vp = V + (size_t)(b * H_ + h) * N_ * D_;

    if (tid < 64) mbS[tid] = d_mb[b * 64 + tid];
    loadsplit(Qp, QH, QL, tid, 4096);
    __syncthreads();

    const uint32_t QHa = smem_u32(QH), QLa = smem_u32(QL);
    const uint32_t KHa = smem_u32(KHp), KLa = smem_u32(KLp);
    const uint32_t VHa = smem_u32(VHp), VLa = smem_u32(VLp);
    const uint32_t koff = (uint32_t)(l7 * 144 + l8 * 2);
    const uint32_t voff = (uint32_t)(l15 * 144);

    // hoist Q fragments (persistent)
    uint32_t aQH[4][4], aQL[4][4];
#pragma unroll
    for (int kk = 0; kk < 4; kk++) {
        uint32_t qo = (uint32_t)((q0w + l15) * 144 + kk * 32 + ((lane & 16) ? 16 : 0));
        ldsm4(aQH[kk], QHa + qo);
        ldsm4(aQL[kk], QLa + qo);
    }

    // ---------- pass 1: row sums ----------
    float lpa = 0.0f, lpb = 0.0f;
    for (int kt = 0; kt < 16; kt++) {
        __syncthreads();
        loadsplit(Kp + (size_t)kt * 128 * D_, KHp, KLp, tid, 2048);
        __syncthreads();
        unsigned int mw[4];
#pragma unroll
        for (int i = 0; i < 4; i++) mw[i] = mbS[kt * 4 + i];
#pragma unroll
        for (int j = 0; j < 8; j++) {
            float c0[4] = {0, 0, 0, 0}, c1[4] = {0, 0, 0, 0};
            uint32_t jo = (uint32_t)j * 2304u + koff;
#pragma unroll
            for (int kk = 0; kk < 4; kk++) {
                uint32_t b0H[2], b0L[2], b1H[2], b1L[2];
                ldsm2(b0H, KHa + jo + kk * 32);
                ldsm2(b0L, KLa + jo + kk * 32);
                ldsm2(b1H, KHa + jo + 1152 + kk * 32);
                ldsm2(b1L, KLa + jo + 1152 + kk * 32);
                mma16816(c0, aQH[kk], b0H[0], b0H[1]);
                mma16816(c0, aQH[kk], b0L[0], b0L[1]);
                mma16816(c0, aQL[kk], b0H[0], b0H[1]);
                mma16816(c1, aQH[kk], b1H[0], b1H[1]);
                mma16816(c1, aQH[kk], b1L[0], b1L[1]);
                mma16816(c1, aQL[kk], b1H[0], b1H[1]);
            }
            unsigned int w = mw[j >> 1];
            int sh = (j & 1) * 16 + 2 * lc;
            if ((w >> sh) & 1)       { lpa += __expf(c0[0] * SCALE); lpb += __expf(c0[2] * SCALE); }
            if ((w >> (sh + 1)) & 1) { lpa += __expf(c0[1] * SCALE); lpb += __expf(c0[3] * SCALE); }
            if ((w >> (sh + 8)) & 1) { lpa += __expf(c1[0] * SCALE); lpb += __expf(c1[2] * SCALE); }
            if ((w >> (sh + 9)) & 1) { lpa += __expf(c1[1] * SCALE); lpb += __expf(c1[3] * SCALE); }
        }
    }
    lpa += __shfl_xor_sync(0xffffffffu, lpa, 1);
    lpa += __shfl_xor_sync(0xffffffffu, lpa, 2);
    lpb += __shfl_xor_sync(0xffffffffu, lpb, 1);
    lpb += __shfl_xor_sync(0xffffffffu, lpb, 2);
    const float invla = 1.0f / lpa;
    const float invlb = 1.0f / lpb;

    // ---------- pass 2: QK recompute -> p_g + PV ----------
    float O[8][4];
#pragma unroll
    for (int n = 0; n < 8; n++)
#pragma unroll
        for (int e = 0; e < 4; e++) O[n][e] = 0.0f;

    float* pga = pg + ((size_t)(b * HG + h) * N_ + q0 + q0w + lq) * N_;
    float* pgb = pga + (size_t)8 * N_;

    for (int kt = 0; kt < 16; kt++) {
        __syncthreads();
        loadsplit(Kp + (size_t)kt * 128 * D_, KHp, KLp, tid, 2048);
        loadsplit(Vp + (size_t)kt * 128 * D_, VHp, VLp, tid, 2048);
        __syncthreads();
        unsigned int mw[4];
#pragma unroll
        for (int i = 0; i < 4; i++) mw[i] = mbS[kt * 4 + i];
#pragma unroll
        for (int j = 0; j < 8; j++) {
            float c0[4] = {0, 0, 0, 0}, c1[4] = {0, 0, 0, 0};
            uint32_t jo = (uint32_t)j * 2304u + koff;
#pragma unroll
            for (int kk = 0; kk < 4; kk++) {
                uint32_t b0H[2], b0L[2], b1H[2], b1L[2];
                ldsm2(b0H, KHa + jo + kk * 32);
                ldsm2(b0L, KLa + jo + kk * 32);
                ldsm2(b1H, KHa + jo + 1152 + kk * 32);
                ldsm2(b1L, KLa + jo + 1152 + kk * 32);
                mma16816(c0, aQH[kk], b0H[0], b0H[1]);
                mma16816(c0, aQH[kk], b0L[0], b0L[1]);
                mma16816(c0, aQL[kk], b0H[0], b0H[1]);
                mma16816(c1, aQH[kk], b1H[0], b1H[1]);
                mma16816(c1, aQH[kk], b1L[0], b1L[1]);
                mma16816(c1, aQL[kk], b1H[0], b1H[1]);
            }
            unsigned int w = mw[j >> 1];
            int sh = (j & 1) * 16 + 2 * lc;
            float p0a0 = ((w >> sh) & 1)       ? __expf(c0[0] * SCALE) * invla : 0.0f;
            float p0a1 = ((w >> (sh + 1)) & 1) ? __expf(c0[1] * SCALE) * invla : 0.0f;
            float p0b0 = ((w >> sh) & 1)       ? __expf(c0[2] * SCALE) * invlb : 0.0f;
            float p0b1 = ((w >> (sh + 1)) & 1) ? __expf(c0[3] * SCALE) * invlb : 0.0f;
            float p1a0 = ((w >> (sh + 8)) & 1) ? __expf(c1[0] * SCALE) * invla : 0.0f;
            float p1a1 = ((w >> (sh + 9)) & 1) ? __expf(c1[1] * SCALE) * invla : 0.0f;
            float p1b0 = ((w >> (sh + 8)) & 1) ? __expf(c1[2] * SCALE) * invlb : 0.0f;
            float p1b1 = ((w >> (sh + 9)) & 1) ? __expf(c1[3] * SCALE) * invlb : 0.0f;

            int ct = kt * 128 + j * 16 + 2 * lc;
            *(float2*)(pga + ct)     = make_float2(p0a0, p0a1);
            *(float2*)(pga + ct + 8) = make_float2(p1a0, p1a1);
            *(float2*)(pgb + ct)     = make_float2(p0b0, p0b1);
            *(float2*)(pgb + ct + 8) = make_float2(p1b0, p1b1);

            // pack P C-frags -> A-frags (hi + lo)
            uint32_t paH[4], paL[4];
            paH[0] = pack2(bhi(p0a0), bhi(p0a1));
            paH[1] = pack2(bhi(p0b0), bhi(p0b1));
            paH[2] = pack2(bhi(p1a0), bhi(p1a1));
            paH[3] = pack2(bhi(p1b0), bhi(p1b1));
            paL[0] = pack2(p0a0 - bhi(p0a0), p0a1 - bhi(p0a1));
            paL[1] = pack2(p0b0 - bhi(p0b0), p0b1 - bhi(p0b1));
            paL[2] = pack2(p1a0 - bhi(p1a0), p1a1 - bhi(p1a1));
            paL[3] = pack2(p1b0 - bhi(p1b0), p1b1 - bhi(p1b1));

            uint32_t vj = (uint32_t)j * 2304u + voff;
#pragma unroll
            for (int n = 0; n < 8; n++) {
                uint32_t vH[2], vL[2];
                ldsm2t(vH, VHa + vj + n * 16);
                ldsm2t(vL, VLa + vj + n * 16);
                mma16816(O[n], paH, vH[0], vH[1]);
                mma16816(O[n], paH, vL[0], vL[1]);
                mma16816(O[n], paL, vH[0], vH[1]);
            }
        }
    }

    float* oa = outp + ((size_t)(b * H_ + h) * N_ + q0 + q0w + lq) * D_;
    float* ob = oa + 8 * D_;
#pragma unroll
    for (int n = 0; n < 8; n++) {
        *(float2*)(oa + n * 8 + 2 * lc) = make_float2(O[n][0], O[n][1]);
        *(float2*)(ob + n * 8 + 2 * lc) = make_float2(O[n][2], O[n][3]);
    }
}

// ---------------------------------------------------------------------------
// Local (banded) heads: warp = q row, d-outer QK with register acc[5].
// ---------------------------------------------------------------------------
__global__ void __launch_bounds__(256) local_kernel(const float* __restrict__ Qm,
                                                    const float* __restrict__ Km,
                                                    const float* __restrict__ Vm,
                                                    float* __restrict__ outp,
                                                    float* __restrict__ pl) {
    __shared__ float KVb[136 * 65];
    __shared__ float Qs[8 * 65];
    __shared__ float pb[8][132];

    const int b = blockIdx.z, hl = blockIdx.y, q0 = blockIdx.x * 8;
    const int h = HG + hl;
    const size_t bh = (size_t)(b * H_ + h);
    const int base = q0 - W_;
    const int tid = threadIdx.x, w = tid >> 5, lane = tid & 31;

    for (int c = tid; c < 8 * 16; c += 256) {
        int r = c >> 4, d4 = (c & 15) << 2;
        float4 v = *(const float4*)(Qm + (bh * N_ + q0 + r) * D_ + d4);
        float* dst = Qs + r * 65 + d4;
        dst[0] = v.x; dst[1] = v.y; dst[2] = v.z; dst[3] = v.w;
    }
    const float* Kp = Km + bh * N_ * D_;
    for (int c = tid; c < 136 * 16; c += 256) {
        int r = c >> 4, d4 = (c & 15) << 2;
        int k = base + r;
        float4 v = make_float4(0.f, 0.f, 0.f, 0.f);
        if (k >= 0 && k < N_) v = *(const float4*)(Kp + (size_t)k * D_ + d4);
        float* dst = KVb + r * 65 + d4;
        dst[0] = v.x; dst[1] = v.y; dst[2] = v.z; dst[3] = v.w;
    }
    __syncthreads();

    const int q = q0 + w;
    float acc[5] = {0.f, 0.f, 0.f, 0.f, 0.f};
    {
        const float* qr = Qs + w * 65;
        const float* kr = KVb + (w + lane) * 65;
#pragma unroll 4
        for (int d = 0; d < D_; d++) {
            float qd = qr[d];
#pragma unroll
            for (int j = 0; j < 4; j++)
                acc[j] += qd * kr[32 * j * 65 + d];
            if (lane == 0) acc[4] += qd * KVb[(w + 128) * 65 + d];
        }
    }
    float sv[5];
#pragma unroll
    for (int j = 0; j < 5; j++) {
        int off = lane + 32 * j;
        if (off <= 2 * W_) {
            int k = base + w + off;
            bool ok = (k >= 0 && k < N_) && (d_mask[b * N_ + k] != 0);
            sv[j] = ok ? acc[j] * SCALE : NEGV;
        } else sv[j] = -3.0e38f;
    }
    float mx = sv[0];
#pragma unroll
    for (int j = 1; j < 5; j++) mx = fmaxf(mx, sv[j]);
#pragma unroll
    for (int o = 16; o >= 1; o >>= 1) mx = fmaxf(mx, __shfl_xor_sync(0xffffffffu, mx, o));
    float es[5], sum = 0.0f;
#pragma unroll
    for (int j = 0; j < 5; j++) { es[j] = __expf(sv[j] - mx); sum += es[j]; }
#pragma unroll
    for (int o = 16; o >= 1; o >>= 1) sum += __shfl_xor_sync(0xffffffffu, sum, o);
    float inv = 1.0f / sum;
#pragma unroll
    for (int j = 0; j < 5; j++) {
        int off = lane + 32 * j;
        if (off <= 2 * W_) pb[w][off] = es[j] * inv;
    }
    __syncwarp();

    const size_t prow = ((size_t)(b * HL + hl) * N_ + q) * N_;
    for (int c = lane; c < N_ / 4; c += 32) {
        int col0 = c * 4;
        float4 v;
        float* vp = &v.x;
#pragma unroll
        for (int t = 0; t < 4; t++) {
            int off = col0 + t - q + W_;
            vp[t] = (off >= 0 && off <= 2 * W_) ? pb[w][off] : 0.0f;
        }
        *(float4*)(&pl[prow + col0]) = v;
    }
    __syncthreads();

    const float* Vp = Vm + bh * N_ * D_;
    for (int c = tid; c < 136 * 16; c += 256) {
        int r = c >> 4, d4 = (c & 15) << 2;
        int k = base + r;
        float4 v = make_float4(0.f, 0.f, 0.f, 0.f);
        if (k >= 0 && k < N_) v = *(const float4*)(Vp + (size_t)k * D_ + d4);
        float* dst = KVb + r * 65 + d4;
        dst[0] = v.x; dst[1] = v.y; dst[2] = v.z; dst[3] = v.w;
    }
    __syncthreads();

    float o0 = 0.0f, o1 = 0.0f;
#pragma unroll 4
    for (int off = 0; off <= 2 * W_; off++) {
        float pv = pb[w][off];
        const float* vr = KVb + (w + off) * 65;
        o0 += pv * vr[lane];
        o1 += pv * vr[32 + lane];
    }
    const size_t obase = (bh * N_ + q) * D_;
    outp[obase + lane] = o0;
    outp[obase + 32 + lane] = o1;
}

// ---------------------------------------------------------------------------
extern "C" void kernel_launch(void* const* d_in, const int* in_sizes, int n_in,
                              void* d_out, int out_size) {
    const float* Q = (const float*)d_in[0];
    const float* K = (const float*)d_in[1];
    const float* V = (const float*)d_in[2];
    const void* mask = d_in[3];

    float* out = (float*)d_out;
    float* pg = out + (size_t)B_ * H_ * N_ * D_;
    float* pl = pg + (size_t)B_ * HG * N_ * N_;

    static int attr_set = 0;
    if (!attr_set) {
        cudaFuncSetAttribute(gattn_kernel, cudaFuncAttributeMaxDynamicSharedMemorySize, SMEM_SZ);
        attr_set = 1;
    }

    prep_mask_kernel<<<1, 256>>>(mask);

    dim3 g1(N_ / 256, HG, B_);
    gattn_kernel<<<g1, 512, SMEM_SZ>>>(Q, K, V, out, pg);

    dim3 g2(N_ / 8, HL, B_);
    local_kernel<<<g2, 256>>>(Q, K, V, out, pl);
}

// round 6
// speedup vs baseline: 2.0543x; 1.1514x over previous
#include <cuda_runtime.h>
#include <cuda_bf16.h>
#include <stdint.h>

#define B_ 2
#define H_ 16
#define N_ 2048
#define D_ 64
#define HG 8
#define HL 8
#define W_ 64
#define SCALE 0.125f

__device__ unsigned int d_mb[B_ * N_ / 32];
__device__ float d_linv[B_ * H_ * N_];

// ---- smem layout (bytes) ----
#define OQH 0u
#define OQL 36864u
#define OKH 73728u
#define OKL 92160u
#define OVH 110592u
#define OVL 129024u
#define OMB 147456u
#define SMEM_SZ 147968

__device__ __forceinline__ uint32_t smem_u32(const void* p) {
    uint32_t a;
    asm("{ .reg .u64 t; cvta.to.shared.u64 t, %1; cvt.u32.u64 %0, t; }" : "=r"(a) : "l"(p));
    return a;
}
__device__ __forceinline__ void ldsm4(uint32_t a[4], uint32_t addr) {
    asm volatile("ldmatrix.sync.aligned.m8n8.x4.shared.b16 {%0,%1,%2,%3}, [%4];"
                 : "=r"(a[0]), "=r"(a[1]), "=r"(a[2]), "=r"(a[3]) : "r"(addr));
}
__device__ __forceinline__ void ldsm2(uint32_t b[2], uint32_t addr) {
    asm volatile("ldmatrix.sync.aligned.m8n8.x2.shared.b16 {%0,%1}, [%2];"
                 : "=r"(b[0]), "=r"(b[1]) : "r"(addr));
}
__device__ __forceinline__ void ldsm2t(uint32_t b[2], uint32_t addr) {
    asm volatile("ldmatrix.sync.aligned.m8n8.x2.trans.shared.b16 {%0,%1}, [%2];"
                 : "=r"(b[0]), "=r"(b[1]) : "r"(addr));
}
__device__ __forceinline__ void mma16816(float c[4], const uint32_t a[4], uint32_t b0, uint32_t b1) {
    asm volatile("mma.sync.aligned.m16n8k16.row.col.f32.bf16.bf16.f32 "
                 "{%0,%1,%2,%3}, {%4,%5,%6,%7}, {%8,%9}, {%0,%1,%2,%3};"
                 : "+f"(c[0]), "+f"(c[1]), "+f"(c[2]), "+f"(c[3])
                 : "r"(a[0]), "r"(a[1]), "r"(a[2]), "r"(a[3]), "r"(b0), "r"(b1));
}
__device__ __forceinline__ uint32_t pack2(float lo, float hi) {
    __nv_bfloat162 t = __floats2bfloat162_rn(lo, hi);
    return *(uint32_t*)&t;
}
__device__ __forceinline__ float bhi(float x) {
    return __bfloat162float(__float2bfloat16(x));
}
__device__ __forceinline__ void split2(float a, float b, uint32_t& hw, uint32_t& lw) {
    __nv_bfloat16 ha = __float2bfloat16(a);
    float fa = __bfloat162float(ha);
    __nv_bfloat16 hb = __float2bfloat16(b);
    float fb = __bfloat162float(hb);
    hw = (uint32_t)__bfloat16_as_ushort(ha) | ((uint32_t)__bfloat16_as_ushort(hb) << 16);
    lw = (uint32_t)__bfloat16_as_ushort(__float2bfloat16(a - fa)) |
         ((uint32_t)__bfloat16_as_ushort(__float2bfloat16(b - fb)) << 16);
}

// one block, 128 threads: each thread builds one 32-bit mask word
__global__ void prep_mask_kernel(const void* __restrict__ mraw) {
    __shared__ int mode;
    if (threadIdx.x == 0) {
        const unsigned int* w = (const unsigned int*)mraw;
        bool ii = true, ff = true;
        for (int i = 0; i < 64; i++) {
            unsigned int v = w[i];
            if (v > 1u) ii = false;
            if (v != 0u && v != 0x3F800000u) ff = false;
        }
        mode = ii ? 1 : (ff ? 2 : 0);
    }
    __syncthreads();
    int m = mode;
    int i = threadIdx.x;          // 0..127
    unsigned int w = 0;
    for (int k = 0; k < 32; k++) {
        int idx = i * 32 + k;
        int v;
        if (m == 1)      v = (((const int*)mraw)[idx] != 0);
        else if (m == 2) v = (((const float*)mraw)[idx] != 0.0f);
        else             v = (((const unsigned char*)mraw)[idx] != 0);
        if (v) w |= 1u << k;
    }
    d_mb[i] = w;
}

// fp32 [rows][64] -> bf16 hi/lo smem (stride 72 elems)
__device__ __forceinline__ void loadsplit(const float* __restrict__ src,
                                          __nv_bfloat16* H, __nv_bfloat16* L,
                                          int tid, int n16) {
    for (int idx = tid; idx < n16; idx += 512) {
        int r = idx >> 4, c4 = (idx & 15) << 2;
        float4 v = *(const float4*)(src + r * D_ + c4);
        uint32_t h01, l01, h23, l23;
        split2(v.x, v.y, h01, l01);
        split2(v.z, v.w, h23, l23);
        uint32_t* hp = (uint32_t*)(H + r * 72 + c4);
        uint32_t* lp = (uint32_t*)(L + r * 72 + c4);
        hp[0] = h01; hp[1] = h23;
        lp[0] = l01; lp[1] = l23;
    }
}

// ---------------------------------------------------------------------------
// Unified single-pass attention (all 16 heads). CTA = 256 q rows of one (b,h).
// Writes UNNORMALIZED exp(s) to pg/pl; O scaled by 1/l in epilogue; 1/l stored.
// Local heads (h>=8): band |q-k|<=64; out-of-range k-tiles skipped/zero-filled.
// ---------------------------------------------------------------------------
__global__ void __launch_bounds__(512, 1)
gattn_kernel(const float* __restrict__ Q, const float* __restrict__ K,
             const float* __restrict__ V, float* __restrict__ outp,
             float* __restrict__ pg, float* __restrict__ pl) {
    extern __shared__ char sm[];
    __nv_bfloat16* QH = (__nv_bfloat16*)(sm + OQH);
    __nv_bfloat16* QL = (__nv_bfloat16*)(sm + OQL);
    __nv_bfloat16* KHp = (__nv_bfloat16*)(sm + OKH);
    __nv_bfloat16* KLp = (__nv_bfloat16*)(sm + OKL);
    __nv_bfloat16* VHp = (__nv_bfloat16*)(sm + OVH);
    __nv_bfloat16* VLp = (__nv_bfloat16*)(sm + OVL);
    unsigned int* mbS = (unsigned int*)(sm + OMB);

    const int b = blockIdx.z, h = blockIdx.y, q0 = blockIdx.x * 256;
    const bool loc = (h >= HG);
    const int tid = threadIdx.x, wq = tid >> 5, lane = tid & 31;
    const int q0w = wq * 16;
    const int l7 = lane & 7, l8 = lane & 8, l15 = lane & 15;
    const int lq = lane >> 2, lc = lane & 3;

    const float* Qp = Q + ((size_t)(b * H_ + h) * N_ + q0) * D_;
    const float* Kp = K + (size_t)(b * H_ + h) * N_ * D_;
    const float* Vp = V + (size_t)(b * H_ + h) * N_ * D_;

    // unnormalized probability destination
    float* prowbase = loc ? pl + ((size_t)(b * HL + (h - HG)) * N_ + q0) * N_
                          : pg + ((size_t)(b * HG + h) * N_ + q0) * N_;
    float* pra = prowbase + (size_t)(q0w + lq) * N_;
    float* prb = pra + (size_t)8 * N_;

    // k-tile range (band for local heads)
    int ktlo = 0, kthi = 15;
    if (loc) {
        int klo = q0 - W_; if (klo < 0) klo = 0;
        int khi = q0 + 255 + W_; if (khi > N_ - 1) khi = N_ - 1;
        ktlo = klo >> 7; kthi = khi >> 7;
    }

    if (tid < 64) mbS[tid] = d_mb[b * 64 + tid];
    loadsplit(Qp, QH, QL, tid, 4096);
    __syncthreads();

    const uint32_t QHa = smem_u32(QH), QLa = smem_u32(QL);
    const uint32_t KHa = smem_u32(KHp), KLa = smem_u32(KLp);
    const uint32_t VHa = smem_u32(VHp), VLa = smem_u32(VLp);
    const uint32_t koff = (uint32_t)(l7 * 144 + l8 * 2);
    const uint32_t voff = (uint32_t)(l15 * 144);

    // hoist Q fragments (persistent)
    uint32_t aQH[4][4], aQL[4][4];
#pragma unroll
    for (int kk = 0; kk < 4; kk++) {
        uint32_t qo = (uint32_t)((q0w + l15) * 144 + kk * 32 + ((lane & 16) ? 16 : 0));
        ldsm4(aQH[kk], QHa + qo);
        ldsm4(aQL[kk], QLa + qo);
    }

    const int qa = q0 + q0w + lq;   // absolute q row (a-half)
    const int qb = qa + 8;
    const int qw0 = q0 + q0w;       // warp's first absolute q row

    float O[8][4];
#pragma unroll
    for (int n = 0; n < 8; n++)
#pragma unroll
        for (int e = 0; e < 4; e++) O[n][e] = 0.0f;
    float lpa = 0.0f, lpb = 0.0f;

    for (int kt = 0; kt < 16; kt++) {
        if (kt < ktlo || kt > kthi) {
            // local head, tile fully out of band: zero-fill pl (block-uniform)
            float4 z = make_float4(0.f, 0.f, 0.f, 0.f);
            for (int idx = tid; idx < 256 * 32; idx += 512) {
                int r = idx >> 5, c4 = (idx & 31) << 2;
                *(float4*)(prowbase + (size_t)r * N_ + kt * 128 + c4) = z;
            }
            continue;
        }
        __syncthreads();
        loadsplit(Kp + (size_t)kt * 128 * D_, KHp, KLp, tid, 2048);
        loadsplit(Vp + (size_t)kt * 128 * D_, VHp, VLp, tid, 2048);
        __syncthreads();
        unsigned int mw[4];
#pragma unroll
        for (int i = 0; i < 4; i++) mw[i] = mbS[kt * 4 + i];
#pragma unroll
        for (int j = 0; j < 8; j++) {
            const int k0j = kt * 128 + j * 16;
            const int ct = k0j + 2 * lc;
            if (loc && !((k0j <= qw0 + 79) && (k0j + 15 >= qw0 - 64))) {
                // j-tile outside warp's band: store zeros
                float2 z2 = make_float2(0.f, 0.f);
                *(float2*)(pra + ct) = z2; *(float2*)(pra + ct + 8) = z2;
                *(float2*)(prb + ct) = z2; *(float2*)(prb + ct + 8) = z2;
                continue;
            }
            float c0[4] = {0, 0, 0, 0}, c1[4] = {0, 0, 0, 0};
            uint32_t jo = (uint32_t)j * 2304u + koff;
#pragma unroll
            for (int kk = 0; kk < 4; kk++) {
                uint32_t b0H[2], b0L[2], b1H[2], b1L[2];
                ldsm2(b0H, KHa + jo + kk * 32);
                ldsm2(b0L, KLa + jo + kk * 32);
                ldsm2(b1H, KHa + jo + 1152 + kk * 32);
                ldsm2(b1L, KLa + jo + 1152 + kk * 32);
                mma16816(c0, aQH[kk], b0H[0], b0H[1]);
                mma16816(c0, aQH[kk], b0L[0], b0L[1]);
                mma16816(c0, aQL[kk], b0H[0], b0H[1]);
                mma16816(c1, aQH[kk], b1H[0], b1H[1]);
                mma16816(c1, aQH[kk], b1L[0], b1L[1]);
                mma16816(c1, aQL[kk], b1H[0], b1H[1]);
            }
            unsigned int w = mw[j >> 1];
            int sh = (j & 1) * 16 + 2 * lc;
            bool m0 = (w >> sh) & 1, m1 = (w >> (sh + 1)) & 1;
            bool m8 = (w >> (sh + 8)) & 1, m9 = (w >> (sh + 9)) & 1;
            // band predicates (true for global heads)
            bool ba0 = !loc || ((unsigned)(ct - qa + 64) <= 128u);
            bool ba1 = !loc || ((unsigned)(ct + 1 - qa + 64) <= 128u);
            bool bb0 = !loc || ((unsigned)(ct - qb + 64) <= 128u);
            bool bb1 = !loc || ((unsigned)(ct + 1 - qb + 64) <= 128u);
            bool ba8 = !loc || ((unsigned)(ct + 8 - qa + 64) <= 128u);
            bool ba9 = !loc || ((unsigned)(ct + 9 - qa + 64) <= 128u);
            bool bb8 = !loc || ((unsigned)(ct + 8 - qb + 64) <= 128u);
            bool bb9 = !loc || ((unsigned)(ct + 9 - qb + 64) <= 128u);

            float p0a0 = (m0 && ba0) ? __expf(c0[0] * SCALE) : 0.0f;
            float p0a1 = (m1 && ba1) ? __expf(c0[1] * SCALE) : 0.0f;
            float p0b0 = (m0 && bb0) ? __expf(c0[2] * SCALE) : 0.0f;
            float p0b1 = (m1 && bb1) ? __expf(c0[3] * SCALE) : 0.0f;
            float p1a0 = (m8 && ba8) ? __expf(c1[0] * SCALE) : 0.0f;
            float p1a1 = (m9 && ba9) ? __expf(c1[1] * SCALE) : 0.0f;
            float p1b0 = (m8 && bb8) ? __expf(c1[2] * SCALE) : 0.0f;
            float p1b1 = (m9 && bb9) ? __expf(c1[3] * SCALE) : 0.0f;

            lpa += (p0a0 + p0a1) + (p1a0 + p1a1);
            lpb += (p0b0 + p0b1) + (p1b0 + p1b1);

            *(float2*)(pra + ct)     = make_float2(p0a0, p0a1);
            *(float2*)(pra + ct + 8) = make_float2(p1a0, p1a1);
            *(float2*)(prb + ct)     = make_float2(p0b0, p0b1);
            *(float2*)(prb + ct + 8) = make_float2(p1b0, p1b1);

            // pack P C-frags -> A-frags (hi + lo)
            uint32_t paH[4], paL[4];
            paH[0] = pack2(bhi(p0a0), bhi(p0a1));
            paH[1] = pack2(bhi(p0b0), bhi(p0b1));
            paH[2] = pack2(bhi(p1a0), bhi(p1a1));
            paH[3] = pack2(bhi(p1b0), bhi(p1b1));
            paL[0] = pack2(p0a0 - bhi(p0a0), p0a1 - bhi(p0a1));
            paL[1] = pack2(p0b0 - bhi(p0b0), p0b1 - bhi(p0b1));
            paL[2] = pack2(p1a0 - bhi(p1a0), p1a1 - bhi(p1a1));
            paL[3] = pack2(p1b0 - bhi(p1b0), p1b1 - bhi(p1b1));

            uint32_t vj = (uint32_t)j * 2304u + voff;
#pragma unroll
            for (int n = 0; n < 8; n++) {
                uint32_t vH[2], vL[2];
                ldsm2t(vH, VHa + vj + n * 16);
                ldsm2t(vL, VLa + vj + n * 16);
                mma16816(O[n], paH, vH[0], vH[1]);
                mma16816(O[n], paH, vL[0], vL[1]);
                mma16816(O[n], paL, vH[0], vH[1]);
            }
        }
    }

    // row sums across the quad (lc = 0..3)
    lpa += __shfl_xor_sync(0xffffffffu, lpa, 1);
    lpa += __shfl_xor_sync(0xffffffffu, lpa, 2);
    lpb += __shfl_xor_sync(0xffffffffu, lpb, 1);
    lpb += __shfl_xor_sync(0xffffffffu, lpb, 2);
    const float invla = (lpa > 0.0f) ? 1.0f / lpa : 0.0f;
    const float invlb = (lpb > 0.0f) ? 1.0f / lpb : 0.0f;

    if (lc == 0) {
        d_linv[(b * H_ + h) * N_ + qa] = invla;
        d_linv[(b * H_ + h) * N_ + qb] = invlb;
    }

    float* oa = outp + ((size_t)(b * H_ + h) * N_ + qa) * D_;
    float* ob = outp + ((size_t)(b * H_ + h) * N_ + qb) * D_;
#pragma unroll
    for (int n = 0; n < 8; n++) {
        *(float2*)(oa + n * 8 + 2 * lc) = make_float2(O[n][0] * invla, O[n][1] * invla);
        *(float2*)(ob + n * 8 + 2 * lc) = make_float2(O[n][2] * invlb, O[n][3] * invlb);
    }
}

// ---------------------------------------------------------------------------
// Normalize pg: one block per row (B*HG*N rows), streaming float4.
// ---------------------------------------------------------------------------
__global__ void __launch_bounds__(128) scale_pg_kernel(float* __restrict__ pg) {
    const int row = blockIdx.x;            // [0, B*HG*N)
    const int b = row >> 14;               // / (HG*N) = 16384
    const int hg = (row >> 11) & 7;
    const int q = row & 2047;
    const float s = d_linv[(b * H_ + hg) * N_ + q];
    float4* p = (float4*)(pg + (size_t)row * N_);
#pragma unroll 4
    for (int i = threadIdx.x; i < N_ / 4; i += 128) {
        float4 v = p[i];
        v.x *= s; v.y *= s; v.z *= s; v.w *= s;
        p[i] = v;
    }
}

// ---------------------------------------------------------------------------
// Normalize pl band only: one block per row (B*HL*N rows), cols [q-64, q+64].
// ---------------------------------------------------------------------------
__global__ void __launch_bounds__(128) scale_pl_kernel(float* __restrict__ pl) {
    const int row = blockIdx.x;            // [0, B*HL*N)
    const int b = row >> 14;
    const int hl = (row >> 11) & 7;
    const int q = row & 2047;
    const float s = d_linv[(b * H_ + HG + hl) * N_ + q];
    int lo = q - W_; if (lo < 0) lo = 0;
    int hi = q + W_; if (hi > N_ - 1) hi = N_ - 1;
    float* p = pl + (size_t)row * N_;
    for (int c = lo + threadIdx.x; c <= hi; c += 128)
        p[c] *= s;
}

// ---------------------------------------------------------------------------
extern "C" void kernel_launch(void* const* d_in, const int* in_sizes, int n_in,
                              void* d_out, int out_size) {
    const float* Q = (const float*)d_in[0];
    const float* K = (const float*)d_in[1];
    const float* V = (const float*)d_in[2];
    const void* mask = d_in[3];

    float* out = (float*)d_out;
    float* pg = out + (size_t)B_ * H_ * N_ * D_;
    float* pl = pg + (size_t)B_ * HG * N_ * N_;

    static int attr_set = 0;
    if (!attr_set) {
        cudaFuncSetAttribute(gattn_kernel, cudaFuncAttributeMaxDynamicSharedMemorySize, SMEM_SZ);
        attr_set = 1;
    }

    prep_mask_kernel<<<1, 128>>>(mask);

    dim3 g1(N_ / 256, H_, B_);
    gattn_kernel<<<g1, 512, SMEM_SZ>>>(Q, K, V, out, pg, pl);

    scale_pg_kernel<<<B_ * HG * N_, 128>>>(pg);
    scale_pl_kernel<<<B_ * HL * N_, 128>>>(pl);
}

// round 7
// speedup vs baseline: 2.1677x; 1.0552x over previous
#include <cuda_runtime.h>
#include <cuda_bf16.h>
#include <stdint.h>

#define B_ 2
#define H_ 16
#define N_ 2048
#define D_ 64
#define HG 8
#define HL 8
#define W_ 64
#define SCALE 0.125f

__device__ unsigned int d_mb[B_ * N_ / 32];
__device__ float d_linv[B_ * H_ * N_];

// ---- smem layout (bytes) ----
// Q: [QH 36864][QL 36864] = 73728
// 2 x KV buffer: [KH 18432][KL 18432][VH 18432][VL 18432] = 73728 each
#define OQH 0u
#define OQL 36864u
#define OBUF 73728u
#define BUFSTRIDE 73728u
#define BKH 0u
#define BKL 18432u
#define BVH 36864u
#define BVL 55296u
#define OMB 221184u
#define SMEM_SZ 221696

__device__ __forceinline__ uint32_t smem_u32(const void* p) {
    uint32_t a;
    asm("{ .reg .u64 t; cvta.to.shared.u64 t, %1; cvt.u32.u64 %0, t; }" : "=r"(a) : "l"(p));
    return a;
}
__device__ __forceinline__ void ldsm4(uint32_t a[4], uint32_t addr) {
    asm volatile("ldmatrix.sync.aligned.m8n8.x4.shared.b16 {%0,%1,%2,%3}, [%4];"
                 : "=r"(a[0]), "=r"(a[1]), "=r"(a[2]), "=r"(a[3]) : "r"(addr));
}
__device__ __forceinline__ void ldsm4t(uint32_t a[4], uint32_t addr) {
    asm volatile("ldmatrix.sync.aligned.m8n8.x4.trans.shared.b16 {%0,%1,%2,%3}, [%4];"
                 : "=r"(a[0]), "=r"(a[1]), "=r"(a[2]), "=r"(a[3]) : "r"(addr));
}
__device__ __forceinline__ void mma16816(float c[4], const uint32_t a[4], uint32_t b0, uint32_t b1) {
    asm volatile("mma.sync.aligned.m16n8k16.row.col.f32.bf16.bf16.f32 "
                 "{%0,%1,%2,%3}, {%4,%5,%6,%7}, {%8,%9}, {%0,%1,%2,%3};"
                 : "+f"(c[0]), "+f"(c[1]), "+f"(c[2]), "+f"(c[3])
                 : "r"(a[0]), "r"(a[1]), "r"(a[2]), "r"(a[3]), "r"(b0), "r"(b1));
}
__device__ __forceinline__ uint32_t pack2(float lo, float hi) {
    __nv_bfloat162 t = __floats2bfloat162_rn(lo, hi);
    return *(uint32_t*)&t;
}
__device__ __forceinline__ float bhi(float x) {
    return __bfloat162float(__float2bfloat16(x));
}
__device__ __forceinline__ void split2(float a, float b, uint32_t& hw, uint32_t& lw) {
    __nv_bfloat16 ha = __float2bfloat16(a);
    float fa = __bfloat162float(ha);
    __nv_bfloat16 hb = __float2bfloat16(b);
    float fb = __bfloat162float(hb);
    hw = (uint32_t)__bfloat16_as_ushort(ha) | ((uint32_t)__bfloat16_as_ushort(hb) << 16);
    lw = (uint32_t)__bfloat16_as_ushort(__float2bfloat16(a - fa)) |
         ((uint32_t)__bfloat16_as_ushort(__float2bfloat16(b - fb)) << 16);
}

// one block, 128 threads: each thread builds one 32-bit mask word
__global__ void prep_mask_kernel(const void* __restrict__ mraw) {
    __shared__ int mode;
    if (threadIdx.x == 0) {
        const unsigned int* w = (const unsigned int*)mraw;
        bool ii = true, ff = true;
        for (int i = 0; i < 64; i++) {
            unsigned int v = w[i];
            if (v > 1u) ii = false;
            if (v != 0u && v != 0x3F800000u) ff = false;
        }
        mode = ii ? 1 : (ff ? 2 : 0);
    }
    __syncthreads();
    int m = mode;
    int i = threadIdx.x;
    unsigned int w = 0;
    for (int k = 0; k < 32; k++) {
        int idx = i * 32 + k;
        int v;
        if (m == 1)      v = (((const int*)mraw)[idx] != 0);
        else if (m == 2) v = (((const float*)mraw)[idx] != 0.0f);
        else             v = (((const unsigned char*)mraw)[idx] != 0);
        if (v) w |= 1u << k;
    }
    d_mb[i] = w;
}

// fp32 [rows][64] -> bf16 hi/lo smem (stride 72 elems)
__device__ __forceinline__ void loadsplit(const float* __restrict__ src,
                                          __nv_bfloat16* H, __nv_bfloat16* L,
                                          int tid, int n16) {
    for (int idx = tid; idx < n16; idx += 512) {
        int r = idx >> 4, c4 = (idx & 15) << 2;
        float4 v = *(const float4*)(src + r * D_ + c4);
        uint32_t h01, l01, h23, l23;
        split2(v.x, v.y, h01, l01);
        split2(v.z, v.w, h23, l23);
        uint32_t* hp = (uint32_t*)(H + r * 72 + c4);
        uint32_t* lp = (uint32_t*)(L + r * 72 + c4);
        hp[0] = h01; hp[1] = h23;
        lp[0] = l01; lp[1] = l23;
    }
}

// ---------------------------------------------------------------------------
// Unified single-pass attention (all 16 heads). CTA = 256 q rows of one (b,h).
// Double-buffered K/V, ldsm x4 with split-lane addressing.
// ---------------------------------------------------------------------------
__global__ void __launch_bounds__(512, 1)
gattn_kernel(const float* __restrict__ Q, const float* __restrict__ K,
             const float* __restrict__ V, float* __restrict__ outp,
             float* __restrict__ pg, float* __restrict__ pl) {
    extern __shared__ char sm[];
    __nv_bfloat16* QH = (__nv_bfloat16*)(sm + OQH);
    __nv_bfloat16* QL = (__nv_bfloat16*)(sm + OQL);
    unsigned int* mbS = (unsigned int*)(sm + OMB);

    const int b = blockIdx.z, h = blockIdx.y, q0 = blockIdx.x * 256;
    const bool loc = (h >= HG);
    const int tid = threadIdx.x, wq = tid >> 5, lane = tid & 31;
    const int q0w = wq * 16;
    const int l7 = lane & 7, l8 = lane & 8, l15 = lane & 15;
    const int lq = lane >> 2, lc = lane & 3;

    const float* Qp = Q + ((size_t)(b * H_ + h) * N_ + q0) * D_;
    const float* Kp = K + (size_t)(b * H_ + h) * N_ * D_;
    const float* Vp = V + (size_t)(b * H_ + h) * N_ * D_;

    float* prowbase = loc ? pl + ((size_t)(b * HL + (h - HG)) * N_ + q0) * N_
                          : pg + ((size_t)(b * HG + h) * N_ + q0) * N_;
    float* pra = prowbase + (size_t)(q0w + lq) * N_;
    float* prb = pra + (size_t)8 * N_;

    // k-tile range (band for local heads)
    int ktlo = 0, kthi = 15;
    if (loc) {
        int klo = q0 - W_; if (klo < 0) klo = 0;
        int khi = q0 + 255 + W_; if (khi > N_ - 1) khi = N_ - 1;
        ktlo = klo >> 7; kthi = khi >> 7;
        // zero-fill fully out-of-band tiles upfront
        float4 z = make_float4(0.f, 0.f, 0.f, 0.f);
        for (int kt = 0; kt < 16; kt++) {
            if (kt >= ktlo && kt <= kthi) continue;
            for (int idx = tid; idx < 256 * 32; idx += 512) {
                int r = idx >> 5, c4 = (idx & 31) << 2;
                *(float4*)(prowbase + (size_t)r * N_ + kt * 128 + c4) = z;
            }
        }
    }

    if (tid < 64) mbS[tid] = d_mb[b * 64 + tid];
    loadsplit(Qp, QH, QL, tid, 4096);
    // prefetch first K/V tile into buffer 0
    {
        char* bb = sm + OBUF;
        loadsplit(Kp + (size_t)ktlo * 128 * D_, (__nv_bfloat16*)(bb + BKH),
                  (__nv_bfloat16*)(bb + BKL), tid, 2048);
        loadsplit(Vp + (size_t)ktlo * 128 * D_, (__nv_bfloat16*)(bb + BVH),
                  (__nv_bfloat16*)(bb + BVL), tid, 2048);
    }
    __syncthreads();

    const uint32_t QHa = smem_u32(QH), QLa = smem_u32(QL);
    const uint32_t BUFa = smem_u32(sm + OBUF);
    // x4 split-lane offsets
    const uint32_t koff4 = (uint32_t)(l7 * 144 + l8 * 2 + (lane & 16) * 72);
    const uint32_t voff4 = (uint32_t)(l15 * 144 + ((lane & 16) ? 18432u : 0u));

    // hoist Q fragments (persistent)
    uint32_t aQH[4][4], aQL[4][4];
#pragma unroll
    for (int kk = 0; kk < 4; kk++) {
        uint32_t qo = (uint32_t)((q0w + l15) * 144 + kk * 32 + ((lane & 16) ? 16 : 0));
        ldsm4(aQH[kk], QHa + qo);
        ldsm4(aQL[kk], QLa + qo);
    }

    const int qa = q0 + q0w + lq;
    const int qb = qa + 8;
    const int qw0 = q0 + q0w;

    float O[8][4];
#pragma unroll
    for (int n = 0; n < 8; n++)
#pragma unroll
        for (int e = 0; e < 4; e++) O[n][e] = 0.0f;
    float lpa = 0.0f, lpb = 0.0f;

    int cur = 0;
    for (int kt = ktlo; kt <= kthi; kt++) {
        // prefetch next tile into the idle buffer
        if (kt < kthi) {
            char* bb = sm + OBUF + (uint32_t)(cur ^ 1) * BUFSTRIDE;
            loadsplit(Kp + (size_t)(kt + 1) * 128 * D_, (__nv_bfloat16*)(bb + BKH),
                      (__nv_bfloat16*)(bb + BKL), tid, 2048);
            loadsplit(Vp + (size_t)(kt + 1) * 128 * D_, (__nv_bfloat16*)(bb + BVH),
                      (__nv_bfloat16*)(bb + BVL), tid, 2048);
        }
        const uint32_t KHa = BUFa + (uint32_t)cur * BUFSTRIDE;       // + BKH
        const uint32_t KLa = KHa + BKL;
        const uint32_t VHa = KHa + BVH;

        unsigned int mw[4];
#pragma unroll
        for (int i = 0; i < 4; i++) mw[i] = mbS[kt * 4 + i];
#pragma unroll
        for (int j = 0; j < 8; j++) {
            const int k0j = kt * 128 + j * 16;
            const int ct = k0j + 2 * lc;
            if (loc && !((k0j <= qw0 + 79) && (k0j + 15 >= qw0 - 64))) {
                float2 z2 = make_float2(0.f, 0.f);
                *(float2*)(pra + ct) = z2; *(float2*)(pra + ct + 8) = z2;
                *(float2*)(prb + ct) = z2; *(float2*)(prb + ct + 8) = z2;
                continue;
            }
            float c0[4] = {0, 0, 0, 0}, c1[4] = {0, 0, 0, 0};
            uint32_t jo = (uint32_t)j * 2304u + koff4;
#pragma unroll
            for (int kk = 0; kk < 4; kk++) {
                uint32_t bH[4], bL[4];
                ldsm4(bH, KHa + jo + kk * 32);
                ldsm4(bL, KLa + jo + kk * 32);
                mma16816(c0, aQH[kk], bH[0], bH[1]);
                mma16816(c0, aQH[kk], bL[0], bL[1]);
                mma16816(c0, aQL[kk], bH[0], bH[1]);
                mma16816(c1, aQH[kk], bH[2], bH[3]);
                mma16816(c1, aQH[kk], bL[2], bL[3]);
                mma16816(c1, aQL[kk], bH[2], bH[3]);
            }
            unsigned int w = mw[j >> 1];
            int sh = (j & 1) * 16 + 2 * lc;
            bool m0 = (w >> sh) & 1, m1 = (w >> (sh + 1)) & 1;
            bool m8 = (w >> (sh + 8)) & 1, m9 = (w >> (sh + 9)) & 1;
            bool ba0 = !loc || ((unsigned)(ct - qa + 64) <= 128u);
            bool ba1 = !loc || ((unsigned)(ct + 1 - qa + 64) <= 128u);
            bool bb0 = !loc || ((unsigned)(ct - qb + 64) <= 128u);
            bool bb1 = !loc || ((unsigned)(ct + 1 - qb + 64) <= 128u);
            bool ba8 = !loc || ((unsigned)(ct + 8 - qa + 64) <= 128u);
            bool ba9 = !loc || ((unsigned)(ct + 9 - qa + 64) <= 128u);
            bool bb8 = !loc || ((unsigned)(ct + 8 - qb + 64) <= 128u);
            bool bb9 = !loc || ((unsigned)(ct + 9 - qb + 64) <= 128u);

            float p0a0 = (m0 && ba0) ? __expf(c0[0] * SCALE) : 0.0f;
            float p0a1 = (m1 && ba1) ? __expf(c0[1] * SCALE) : 0.0f;
            float p0b0 = (m0 && bb0) ? __expf(c0[2] * SCALE) : 0.0f;
            float p0b1 = (m1 && bb1) ? __expf(c0[3] * SCALE) : 0.0f;
            float p1a0 = (m8 && ba8) ? __expf(c1[0] * SCALE) : 0.0f;
            float p1a1 = (m9 && ba9) ? __expf(c1[1] * SCALE) : 0.0f;
            float p1b0 = (m8 && bb8) ? __expf(c1[2] * SCALE) : 0.0f;
            float p1b1 = (m9 && bb9) ? __expf(c1[3] * SCALE) : 0.0f;

            lpa += (p0a0 + p0a1) + (p1a0 + p1a1);
            lpb += (p0b0 + p0b1) + (p1b0 + p1b1);

            *(float2*)(pra + ct)     = make_float2(p0a0, p0a1);
            *(float2*)(pra + ct + 8) = make_float2(p1a0, p1a1);
            *(float2*)(prb + ct)     = make_float2(p0b0, p0b1);
            *(float2*)(prb + ct + 8) = make_float2(p1b0, p1b1);

            uint32_t paH[4], paL[4];
            paH[0] = pack2(bhi(p0a0), bhi(p0a1));
            paH[1] = pack2(bhi(p0b0), bhi(p0b1));
            paH[2] = pack2(bhi(p1a0), bhi(p1a1));
            paH[3] = pack2(bhi(p1b0), bhi(p1b1));
            paL[0] = pack2(p0a0 - bhi(p0a0), p0a1 - bhi(p0a1));
            paL[1] = pack2(p0b0 - bhi(p0b0), p0b1 - bhi(p0b1));
            paL[2] = pack2(p1a0 - bhi(p1a0), p1a1 - bhi(p1a1));
            paL[3] = pack2(p1b0 - bhi(p1b0), p1b1 - bhi(p1b1));

            uint32_t vj = (uint32_t)j * 2304u + voff4;
#pragma unroll
            for (int n = 0; n < 8; n++) {
                uint32_t v4[4];
                ldsm4t(v4, VHa + vj + n * 16);
                mma16816(O[n], paH, v4[0], v4[1]);
                mma16816(O[n], paH, v4[2], v4[3]);
                mma16816(O[n], paL, v4[0], v4[1]);
            }
        }
        __syncthreads();
        cur ^= 1;
    }

    lpa += __shfl_xor_sync(0xffffffffu, lpa, 1);
    lpa += __shfl_xor_sync(0xffffffffu, lpa, 2);
    lpb += __shfl_xor_sync(0xffffffffu, lpb, 1);
    lpb += __shfl_xor_sync(0xffffffffu, lpb, 2);
    const float invla = (lpa > 0.0f) ? 1.0f / lpa : 0.0f;
    const float invlb = (lpb > 0.0f) ? 1.0f / lpb : 0.0f;

    if (lc == 0) {
        d_linv[(b * H_ + h) * N_ + qa] = invla;
        d_linv[(b * H_ + h) * N_ + qb] = invlb;
    }

    float* oa = outp + ((size_t)(b * H_ + h) * N_ + qa) * D_;
    float* ob = outp + ((size_t)(b * H_ + h) * N_ + qb) * D_;
#pragma unroll
    for (int n = 0; n < 8; n++) {
        *(float2*)(oa + n * 8 + 2 * lc) = make_float2(O[n][0] * invla, O[n][1] * invla);
        *(float2*)(ob + n * 8 + 2 * lc) = make_float2(O[n][2] * invlb, O[n][3] * invlb);
    }
}

// ---------------------------------------------------------------------------
__global__ void __launch_bounds__(128) scale_pg_kernel(float* __restrict__ pg) {
    const int row = blockIdx.x;
    const int b = row >> 14;
    const int hg = (row >> 11) & 7;
    const int q = row & 2047;
    const float s = d_linv[(b * H_ + hg) * N_ + q];
    float4* p = (float4*)(pg + (size_t)row * N_);
#pragma unroll 4
    for (int i = threadIdx.x; i < N_ / 4; i += 128) {
        float4 v = p[i];
        v.x *= s; v.y *= s; v.z *= s; v.w *= s;
        p[i] = v;
    }
}

__global__ void __launch_bounds__(128) scale_pl_kernel(float* __restrict__ pl) {
    const int row = blockIdx.x;
    const int b = row >> 14;
    const int hl = (row >> 11) & 7;
    const int q = row & 2047;
    const float s = d_linv[(b * H_ + HG + hl) * N_ + q];
    int lo = q - W_; if (lo < 0) lo = 0;
    int hi = q + W_; if (hi > N_ - 1) hi = N_ - 1;
    float* p = pl + (size_t)row * N_;
    for (int c = lo + threadIdx.x; c <= hi; c += 128)
        p[c] *= s;
}

// ---------------------------------------------------------------------------
extern "C" void kernel_launch(void* const* d_in, const int* in_sizes, int n_in,
                              void* d_out, int out_size) {
    const float* Q = (const float*)d_in[0];
    const float* K = (const float*)d_in[1];
    const float* V = (const float*)d_in[2];
    const void* mask = d_in[3];

    float* out = (float*)d_out;
    float* pg = out + (size_t)B_ * H_ * N_ * D_;
    float* pl = pg + (size_t)B_ * HG * N_ * N_;

    static int attr_set = 0;
    if (!attr_set) {
        cudaFuncSetAttribute(gattn_kernel, cudaFuncAttributeMaxDynamicSharedMemorySize, SMEM_SZ);
        attr_set = 1;
    }

    prep_mask_kernel<<<1, 128>>>(mask);

    dim3 g1(N_ / 256, H_, B_);
    gattn_kernel<<<g1, 512, SMEM_SZ>>>(Q, K, V, out, pg, pl);

    scale_pg_kernel<<<B_ * HG * N_, 128>>>(pg);
    scale_pl_kernel<<<B_ * HL * N_, 128>>>(pl);
}

// round 8
// speedup vs baseline: 2.7008x; 1.2460x over previous
#include <cuda_runtime.h>
#include <cuda_bf16.h>
#include <stdint.h>

#define B_ 2
#define H_ 16
#define N_ 2048
#define D_ 64
#define HG 8
#define HL 8
#define W_ 64
#define SCALE 0.125f

__device__ unsigned int d_mb[B_ * 64];
__device__ float d_linv[B_ * H_ * N_];
__device__ int d_pos[B_ * N_];
__device__ int d_idx[B_ * N_];
__device__ int d_cnt[B_];
__device__ float d_pgc[(size_t)B_ * HG * N_ * N_];
__device__ __nv_bfloat16 d_kch[(size_t)B_ * HG * N_ * D_];
__device__ __nv_bfloat16 d_kcl[(size_t)B_ * HG * N_ * D_];
__device__ __nv_bfloat16 d_vch[(size_t)B_ * HG * N_ * D_];
__device__ __nv_bfloat16 d_vcl[(size_t)B_ * HG * N_ * D_];

// ---- smem layout (bytes) ----
#define OQH 0u
#define OQL 36864u
#define OBUF 73728u
#define BUFSTRIDE 73728u
#define BKH 0u
#define BKL 18432u
#define BVH 36864u
#define BVL 55296u
#define OMB 221184u
#define SMEM_SZ 221696

__device__ __forceinline__ uint32_t smem_u32(const void* p) {
    uint32_t a;
    asm("{ .reg .u64 t; cvta.to.shared.u64 t, %1; cvt.u32.u64 %0, t; }" : "=r"(a) : "l"(p));
    return a;
}
__device__ __forceinline__ void ldsm4(uint32_t a[4], uint32_t addr) {
    asm volatile("ldmatrix.sync.aligned.m8n8.x4.shared.b16 {%0,%1,%2,%3}, [%4];"
                 : "=r"(a[0]), "=r"(a[1]), "=r"(a[2]), "=r"(a[3]) : "r"(addr));
}
__device__ __forceinline__ void ldsm4t(uint32_t a[4], uint32_t addr) {
    asm volatile("ldmatrix.sync.aligned.m8n8.x4.trans.shared.b16 {%0,%1,%2,%3}, [%4];"
                 : "=r"(a[0]), "=r"(a[1]), "=r"(a[2]), "=r"(a[3]) : "r"(addr));
}
__device__ __forceinline__ void mma16816(float c[4], const uint32_t a[4], uint32_t b0, uint32_t b1) {
    asm volatile("mma.sync.aligned.m16n8k16.row.col.f32.bf16.bf16.f32 "
                 "{%0,%1,%2,%3}, {%4,%5,%6,%7}, {%8,%9}, {%0,%1,%2,%3};"
                 : "+f"(c[0]), "+f"(c[1]), "+f"(c[2]), "+f"(c[3])
                 : "r"(a[0]), "r"(a[1]), "r"(a[2]), "r"(a[3]), "r"(b0), "r"(b1));
}
__device__ __forceinline__ uint32_t pack2(float lo, float hi) {
    __nv_bfloat162 t = __floats2bfloat162_rn(lo, hi);
    return *(uint32_t*)&t;
}
__device__ __forceinline__ float bhi(float x) {
    return __bfloat162float(__float2bfloat16(x));
}
__device__ __forceinline__ void split2(float a, float b, uint32_t& hw, uint32_t& lw) {
    __nv_bfloat16 ha = __float2bfloat16(a);
    float fa = __bfloat162float(ha);
    __nv_bfloat16 hb = __float2bfloat16(b);
    float fb = __bfloat162float(hb);
    hw = (uint32_t)__bfloat16_as_ushort(ha) | ((uint32_t)__bfloat16_as_ushort(hb) << 16);
    lw = (uint32_t)__bfloat16_as_ushort(__float2bfloat16(a - fa)) |
         ((uint32_t)__bfloat16_as_ushort(__float2bfloat16(b - fb)) << 16);
}

// ---------------------------------------------------------------------------
// prep: mask dtype detect, bitmask, per-batch compaction map (idx/pos/cnt)
// ---------------------------------------------------------------------------
__global__ void prep_mask_kernel(const void* __restrict__ mraw) {
    __shared__ int mode;
    __shared__ int cnt_s[256];
    __shared__ int off_s[256];
    const int t = threadIdx.x;   // 256 threads
    if (t == 0) {
        const unsigned int* w = (const unsigned int*)mraw;
        bool ii = true, ff = true;
        for (int i = 0; i < 64; i++) {
            unsigned int v = w[i];
            if (v > 1u) ii = false;
            if (v != 0u && v != 0x3F800000u) ff = false;
        }
        mode = ii ? 1 : (ff ? 2 : 0);
    }
    __syncthreads();
    int m = mode;
    if (t < 128) {
        unsigned int w = 0;
        for (int k = 0; k < 32; k++) {
            int idx = t * 32 + k;
            int v;
            if (m == 1)      v = (((const int*)mraw)[idx] != 0);
            else if (m == 2) v = (((const float*)mraw)[idx] != 0.0f);
            else             v = (((const unsigned char*)mraw)[idx] != 0);
            if (v) w |= 1u << k;
        }
        d_mb[t] = w;
    }
    __syncthreads();
    for (int b = 0; b < B_; b++) {
        unsigned int word = d_mb[b * 64 + (t >> 2)];
        unsigned int byte = (word >> ((t & 3) * 8)) & 0xFFu;
        cnt_s[t] = __popc(byte);
        __syncthreads();
        if (t == 0) {
            int run = 0;
            for (int i = 0; i < 256; i++) { off_s[i] = run; run += cnt_s[i]; }
            d_cnt[b] = run;
        }
        __syncthreads();
        int p = off_s[t];
        for (int k = 0; k < 8; k++) {
            int c = t * 8 + k;
            if ((byte >> k) & 1) {
                d_idx[b * N_ + p] = c;
                d_pos[b * N_ + c] = p;
                p++;
            } else {
                d_pos[b * N_ + c] = 0;
            }
        }
        __syncthreads();
    }
}

// ---------------------------------------------------------------------------
// gather unmasked K/V rows -> pre-split bf16 hi/lo compact buffers (+zero pad)
// ---------------------------------------------------------------------------
__global__ void __launch_bounds__(256) compact_kv_kernel(const float* __restrict__ K,
                                                         const float* __restrict__ V) {
    const int b = blockIdx.z, h = blockIdx.y, jt = blockIdx.x;
    const int cnt = d_cnt[b];
    const int cnt_pad = (cnt + 127) & ~127;
    const int j0 = jt * 128;
    if (j0 >= cnt_pad) return;
    const size_t obase = (size_t)(b * HG + h) * N_ * D_;
    for (int idx = threadIdx.x; idx < 128 * 16; idx += 256) {
        int r = idx >> 4, c4 = (idx & 15) << 2;
        int j = j0 + r;
        float4 kv = make_float4(0.f, 0.f, 0.f, 0.f);
        float4 vv = make_float4(0.f, 0.f, 0.f, 0.f);
        if (j < cnt) {
            int src = d_idx[b * N_ + j];
            size_t sb = ((size_t)(b * H_ + h) * N_ + src) * D_ + c4;
            kv = *(const float4*)(K + sb);
            vv = *(const float4*)(V + sb);
        }
        size_t off = obase + (size_t)j * D_ + c4;
        uint32_t h01, l01, h23, l23;
        split2(kv.x, kv.y, h01, l01); split2(kv.z, kv.w, h23, l23);
        *(uint2*)(d_kch + off) = make_uint2(h01, h23);
        *(uint2*)(d_kcl + off) = make_uint2(l01, l23);
        split2(vv.x, vv.y, h01, l01); split2(vv.z, vv.w, h23, l23);
        *(uint2*)(d_vch + off) = make_uint2(h01, h23);
        *(uint2*)(d_vcl + off) = make_uint2(l01, l23);
    }
}

// fp32 [rows][64] -> bf16 hi/lo smem (stride 72 elems)
__device__ __forceinline__ void loadsplit(const float* __restrict__ src,
                                          __nv_bfloat16* H, __nv_bfloat16* L,
                                          int tid, int n16) {
    for (int idx = tid; idx < n16; idx += 512) {
        int r = idx >> 4, c4 = (idx & 15) << 2;
        float4 v = *(const float4*)(src + r * D_ + c4);
        uint32_t h01, l01, h23, l23;
        split2(v.x, v.y, h01, l01);
        split2(v.z, v.w, h23, l23);
        uint32_t* hp = (uint32_t*)(H + r * 72 + c4);
        uint32_t* lp = (uint32_t*)(L + r * 72 + c4);
        hp[0] = h01; hp[1] = h23;
        lp[0] = l01; lp[1] = l23;
    }
}

// bf16 compact [128][64] -> smem stride-72 copy
__device__ __forceinline__ void loadcopy(const __nv_bfloat16* __restrict__ src,
                                         char* dst, int tid) {
    const uint4* s4 = (const uint4*)src;
    for (int idx = tid; idx < 1024; idx += 512) {
        int r = idx >> 3, c8 = idx & 7;
        uint4 v = s4[r * 8 + c8];
        *(uint4*)(dst + r * 144 + c8 * 16) = v;
    }
}

// ---------------------------------------------------------------------------
// Global heads over COMPACTED keys. CTA = 256 q rows of one (b,h<8).
// ---------------------------------------------------------------------------
__global__ void __launch_bounds__(512, 1)
gattn_global_kernel(const float* __restrict__ Q, float* __restrict__ outp) {
    extern __shared__ char sm[];
    __nv_bfloat16* QH = (__nv_bfloat16*)(sm + OQH);
    __nv_bfloat16* QL = (__nv_bfloat16*)(sm + OQL);

    const int b = blockIdx.z, h = blockIdx.y, q0 = blockIdx.x * 256;
    const int tid = threadIdx.x, wq = tid >> 5, lane = tid & 31;
    const int q0w = wq * 16;
    const int l7 = lane & 7, l8 = lane & 8, l15 = lane & 15;
    const int lq = lane >> 2, lc = lane & 3;

    const int cnt = d_cnt[b];
    const int ktn = (cnt + 127) >> 7;

    const float* Qp = Q + ((size_t)(b * H_ + h) * N_ + q0) * D_;
    const __nv_bfloat16* Kh = d_kch + (size_t)(b * HG + h) * N_ * D_;
    const __nv_bfloat16* Kl = d_kcl + (size_t)(b * HG + h) * N_ * D_;
    const __nv_bfloat16* Vh = d_vch + (size_t)(b * HG + h) * N_ * D_;
    const __nv_bfloat16* Vl = d_vcl + (size_t)(b * HG + h) * N_ * D_;

    float* pra = d_pgc + ((size_t)(b * HG + h) * N_ + q0 + q0w + lq) * N_;
    float* prb = pra + (size_t)8 * N_;

    loadsplit(Qp, QH, QL, tid, 4096);
    {
        char* bb = sm + OBUF;
        loadcopy(Kh, bb + BKH, tid);
        loadcopy(Kl, bb + BKL, tid);
        loadcopy(Vh, bb + BVH, tid);
        loadcopy(Vl, bb + BVL, tid);
    }
    __syncthreads();

    const uint32_t QHa = smem_u32(QH), QLa = smem_u32(QL);
    const uint32_t BUFa = smem_u32(sm + OBUF);
    const uint32_t koff4 = (uint32_t)(l7 * 144 + l8 * 2 + (lane & 16) * 72);
    const uint32_t voff4 = (uint32_t)(l15 * 144 + ((lane & 16) ? 18432u : 0u));

    uint32_t aQH[4][4], aQL[4][4];
#pragma unroll
    for (int kk = 0; kk < 4; kk++) {
        uint32_t qo = (uint32_t)((q0w + l15) * 144 + kk * 32 + ((lane & 16) ? 16 : 0));
        ldsm4(aQH[kk], QHa + qo);
        ldsm4(aQL[kk], QLa + qo);
    }

    const int qa = q0 + q0w + lq;
    const int qb = qa + 8;

    float O[8][4];
#pragma unroll
    for (int n = 0; n < 8; n++)
#pragma unroll
        for (int e = 0; e < 4; e++) O[n][e] = 0.0f;
    float lpa = 0.0f, lpb = 0.0f;

    int cur = 0;
    for (int kt = 0; kt < ktn; kt++) {
        if (kt + 1 < ktn) {
            char* bb = sm + OBUF + (uint32_t)(cur ^ 1) * BUFSTRIDE;
            size_t t0 = (size_t)(kt + 1) * 128 * D_;
            loadcopy(Kh + t0, bb + BKH, tid);
            loadcopy(Kl + t0, bb + BKL, tid);
            loadcopy(Vh + t0, bb + BVH, tid);
            loadcopy(Vl + t0, bb + BVL, tid);
        }
        const uint32_t KHa = BUFa + (uint32_t)cur * BUFSTRIDE;
        const uint32_t KLa = KHa + BKL;
        const uint32_t VHa = KHa + BVH;

#pragma unroll
        for (int j = 0; j < 8; j++) {
            const int ct = kt * 128 + j * 16 + 2 * lc;
            float c0[4] = {0, 0, 0, 0}, c1[4] = {0, 0, 0, 0};
            uint32_t jo = (uint32_t)j * 2304u + koff4;
#pragma unroll
            for (int kk = 0; kk < 4; kk++) {
                uint32_t bH[4], bL[4];
                ldsm4(bH, KHa + jo + kk * 32);
                ldsm4(bL, KLa + jo + kk * 32);
                mma16816(c0, aQH[kk], bH[0], bH[1]);
                mma16816(c0, aQH[kk], bL[0], bL[1]);
                mma16816(c0, aQL[kk], bH[0], bH[1]);
                mma16816(c1, aQH[kk], bH[2], bH[3]);
                mma16816(c1, aQH[kk], bL[2], bL[3]);
                mma16816(c1, aQL[kk], bH[2], bH[3]);
            }
            bool m0 = (ct < cnt), m1 = (ct + 1 < cnt);
            bool m8 = (ct + 8 < cnt), m9 = (ct + 9 < cnt);
            float p0a0 = m0 ? __expf(c0[0] * SCALE) : 0.0f;
            float p0a1 = m1 ? __expf(c0[1] * SCALE) : 0.0f;
            float p0b0 = m0 ? __expf(c0[2] * SCALE) : 0.0f;
            float p0b1 = m1 ? __expf(c0[3] * SCALE) : 0.0f;
            float p1a0 = m8 ? __expf(c1[0] * SCALE) : 0.0f;
            float p1a1 = m9 ? __expf(c1[1] * SCALE) : 0.0f;
            float p1b0 = m8 ? __expf(c1[2] * SCALE) : 0.0f;
            float p1b1 = m9 ? __expf(c1[3] * SCALE) : 0.0f;

            lpa += (p0a0 + p0a1) + (p1a0 + p1a1);
            lpb += (p0b0 + p0b1) + (p1b0 + p1b1);

            *(float2*)(pra + ct)     = make_float2(p0a0, p0a1);
            *(float2*)(pra + ct + 8) = make_float2(p1a0, p1a1);
            *(float2*)(prb + ct)     = make_float2(p0b0, p0b1);
            *(float2*)(prb + ct + 8) = make_float2(p1b0, p1b1);

            uint32_t paH[4], paL[4];
            paH[0] = pack2(bhi(p0a0), bhi(p0a1));
            paH[1] = pack2(bhi(p0b0), bhi(p0b1));
            paH[2] = pack2(bhi(p1a0), bhi(p1a1));
            paH[3] = pack2(bhi(p1b0), bhi(p1b1));
            paL[0] = pack2(p0a0 - bhi(p0a0), p0a1 - bhi(p0a1));
            paL[1] = pack2(p0b0 - bhi(p0b0), p0b1 - bhi(p0b1));
            paL[2] = pack2(p1a0 - bhi(p1a0), p1a1 - bhi(p1a1));
            paL[3] = pack2(p1b0 - bhi(p1b0), p1b1 - bhi(p1b1));

            uint32_t vj = (uint32_t)j * 2304u + voff4;
#pragma unroll
            for (int n = 0; n < 8; n++) {
                uint32_t v4[4];
                ldsm4t(v4, VHa + vj + n * 16);
                mma16816(O[n], paH, v4[0], v4[1]);
                mma16816(O[n], paH, v4[2], v4[3]);
                mma16816(O[n], paL, v4[0], v4[1]);
            }
        }
        __syncthreads();
        cur ^= 1;
    }

    lpa += __shfl_xor_sync(0xffffffffu, lpa, 1);
    lpa += __shfl_xor_sync(0xffffffffu, lpa, 2);
    lpb += __shfl_xor_sync(0xffffffffu, lpb, 1);
    lpb += __shfl_xor_sync(0xffffffffu, lpb, 2);
    const float invla = (lpa > 0.0f) ? 1.0f / lpa : 0.0f;
    const float invlb = (lpb > 0.0f) ? 1.0f / lpb : 0.0f;

    if (lc == 0) {
        d_linv[(b * H_ + h) * N_ + qa] = invla;
        d_linv[(b * H_ + h) * N_ + qb] = invlb;
    }

    float* oa = outp + ((size_t)(b * H_ + h) * N_ + qa) * D_;
    float* ob = outp + ((size_t)(b * H_ + h) * N_ + qb) * D_;
#pragma unroll
    for (int n = 0; n < 8; n++) {
        *(float2*)(oa + n * 8 + 2 * lc) = make_float2(O[n][0] * invla, O[n][1] * invla);
        *(float2*)(ob + n * 8 + 2 * lc) = make_float2(O[n][2] * invlb, O[n][3] * invlb);
    }
}

// ---------------------------------------------------------------------------
// Local (banded) heads, original key space. CTA = 256 q rows of one local head.
// ---------------------------------------------------------------------------
__global__ void __launch_bounds__(512, 1)
gattn_local_kernel(const float* __restrict__ Q, const float* __restrict__ K,
                   const float* __restrict__ V, float* __restrict__ outp,
                   float* __restrict__ pl) {
    extern __shared__ char sm[];
    __nv_bfloat16* QH = (__nv_bfloat16*)(sm + OQH);
    __nv_bfloat16* QL = (__nv_bfloat16*)(sm + OQL);
    unsigned int* mbS = (unsigned int*)(sm + OMB);

    const int b = blockIdx.z, hy = blockIdx.y, q0 = blockIdx.x * 256;
    const int h = HG + hy;
    const int tid = threadIdx.x, wq = tid >> 5, lane = tid & 31;
    const int q0w = wq * 16;
    const int l7 = lane & 7, l8 = lane & 8, l15 = lane & 15;
    const int lq = lane >> 2, lc = lane & 3;

    const float* Qp = Q + ((size_t)(b * H_ + h) * N_ + q0) * D_;
    const float* Kp = K + (size_t)(b * H_ + h) * N_ * D_;
    const float* Vp = V + (size_t)(b * H_ + h) * N_ * D_;

    float* prowbase = pl + ((size_t)(b * HL + hy) * N_ + q0) * N_;
    float* pra = prowbase + (size_t)(q0w + lq) * N_;
    float* prb = pra + (size_t)8 * N_;

    int klo = q0 - W_; if (klo < 0) klo = 0;
    int khi = q0 + 255 + W_; if (khi > N_ - 1) khi = N_ - 1;
    const int ktlo = klo >> 7, kthi = khi >> 7;
    {
        float4 z = make_float4(0.f, 0.f, 0.f, 0.f);
        for (int kt = 0; kt < 16; kt++) {
            if (kt >= ktlo && kt <= kthi) continue;
            for (int idx = tid; idx < 256 * 32; idx += 512) {
                int r = idx >> 5, c4 = (idx & 31) << 2;
                *(float4*)(prowbase + (size_t)r * N_ + kt * 128 + c4) = z;
            }
        }
    }

    if (tid < 64) mbS[tid] = d_mb[b * 64 + tid];
    loadsplit(Qp, QH, QL, tid, 4096);
    {
        char* bb = sm + OBUF;
        loadsplit(Kp + (size_t)ktlo * 128 * D_, (__nv_bfloat16*)(bb + BKH),
                  (__nv_bfloat16*)(bb + BKL), tid, 2048);
        loadsplit(Vp + (size_t)ktlo * 128 * D_, (__nv_bfloat16*)(bb + BVH),
                  (__nv_bfloat16*)(bb + BVL), tid, 2048);
    }
    __syncthreads();

    const uint32_t QHa = smem_u32(QH), QLa = smem_u32(QL);
    const uint32_t BUFa = smem_u32(sm + OBUF);
    const uint32_t koff4 = (uint32_t)(l7 * 144 + l8 * 2 + (lane & 16) * 72);
    const uint32_t voff4 = (uint32_t)(l15 * 144 + ((lane & 16) ? 18432u : 0u));

    uint32_t aQH[4][4], aQL[4][4];
#pragma unroll
    for (int kk = 0; kk < 4; kk++) {
        uint32_t qo = (uint32_t)((q0w + l15) * 144 + kk * 32 + ((lane & 16) ? 16 : 0));
        ldsm4(aQH[kk], QHa + qo);
        ldsm4(aQL[kk], QLa + qo);
    }

    const int qa = q0 + q0w + lq;
    const int qb = qa + 8;
    const int qw0 = q0 + q0w;

    float O[8][4];
#pragma unroll
    for (int n = 0; n < 8; n++)
#pragma unroll
        for (int e = 0; e < 4; e++) O[n][e] = 0.0f;
    float lpa = 0.0f, lpb = 0.0f;

    int cur = 0;
    for (int kt = ktlo; kt <= kthi; kt++) {
        if (kt < kthi) {
            char* bb = sm + OBUF + (uint32_t)(cur ^ 1) * BUFSTRIDE;
            loadsplit(Kp + (size_t)(kt + 1) * 128 * D_, (__nv_bfloat16*)(bb + BKH),
                      (__nv_bfloat16*)(bb + BKL), tid, 2048);
            loadsplit(Vp + (size_t)(kt + 1) * 128 * D_, (__nv_bfloat16*)(bb + BVH),
                      (__nv_bfloat16*)(bb + BVL), tid, 2048);
        }
        const uint32_t KHa = BUFa + (uint32_t)cur * BUFSTRIDE;
        const uint32_t KLa = KHa + BKL;
        const uint32_t VHa = KHa + BVH;

        unsigned int mw[4];
#pragma unroll
        for (int i = 0; i < 4; i++) mw[i] = mbS[kt * 4 + i];
#pragma unroll
        for (int j = 0; j < 8; j++) {
            const int k0j = kt * 128 + j * 16;
            const int ct = k0j + 2 * lc;
            if (!((k0j <= qw0 + 79) && (k0j + 15 >= qw0 - 64))) {
                float2 z2 = make_float2(0.f, 0.f);
                *(float2*)(pra + ct) = z2; *(float2*)(pra + ct + 8) = z2;
                *(float2*)(prb + ct) = z2; *(float2*)(prb + ct + 8) = z2;
                continue;
            }
            float c0[4] = {0, 0, 0, 0}, c1[4] = {0, 0, 0, 0};
            uint32_t jo = (uint32_t)j * 2304u + koff4;
#pragma unroll
            for (int kk = 0; kk < 4; kk++) {
                uint32_t bH[4], bL[4];
                ldsm4(bH, KHa + jo + kk * 32);
                ldsm4(bL, KLa + jo + kk * 32);
                mma16816(c0, aQH[kk], bH[0], bH[1]);
                mma16816(c0, aQH[kk], bL[0], bL[1]);
                mma16816(c0, aQL[kk], bH[0], bH[1]);
                mma16816(c1, aQH[kk], bH[2], bH[3]);
                mma16816(c1, aQH[kk], bL[2], bL[3]);
                mma16816(c1, aQL[kk], bH[2], bH[3]);
            }
            unsigned int w = mw[j >> 1];
            int sh = (j & 1) * 16 + 2 * lc;
            bool m0 = (w >> sh) & 1, m1 = (w >> (sh + 1)) & 1;
            bool m8 = (w >> (sh + 8)) & 1, m9 = (w >> (sh + 9)) & 1;
            bool ba0 = ((unsigned)(ct - qa + 64) <= 128u);
            bool ba1 = ((unsigned)(ct + 1 - qa + 64) <= 128u);
            bool bb0 = ((unsigned)(ct - qb + 64) <= 128u);
            bool bb1 = ((unsigned)(ct + 1 - qb + 64) <= 128u);
            bool ba8 = ((unsigned)(ct + 8 - qa + 64) <= 128u);
            bool ba9 = ((unsigned)(ct + 9 - qa + 64) <= 128u);
            bool bb8 = ((unsigned)(ct + 8 - qb + 64) <= 128u);
            bool bb9 = ((unsigned)(ct + 9 - qb + 64) <= 128u);

            float p0a0 = (m0 && ba0) ? __expf(c0[0] * SCALE) : 0.0f;
            float p0a1 = (m1 && ba1) ? __expf(c0[1] * SCALE) : 0.0f;
            float p0b0 = (m0 && bb0) ? __expf(c0[2] * SCALE) : 0.0f;
            float p0b1 = (m1 && bb1) ? __expf(c0[3] * SCALE) : 0.0f;
            float p1a0 = (m8 && ba8) ? __expf(c1[0] * SCALE) : 0.0f;
            float p1a1 = (m9 && ba9) ? __expf(c1[1] * SCALE) : 0.0f;
            float p1b0 = (m8 && bb8) ? __expf(c1[2] * SCALE) : 0.0f;
            float p1b1 = (m9 && bb9) ? __expf(c1[3] * SCALE) : 0.0f;

            lpa += (p0a0 + p0a1) + (p1a0 + p1a1);
            lpb += (p0b0 + p0b1) + (p1b0 + p1b1);

            *(float2*)(pra + ct)     = make_float2(p0a0, p0a1);
            *(float2*)(pra + ct + 8) = make_float2(p1a0, p1a1);
            *(float2*)(prb + ct)     = make_float2(p0b0, p0b1);
            *(float2*)(prb + ct + 8) = make_float2(p1b0, p1b1);

            uint32_t paH[4], paL[4];
            paH[0] = pack2(bhi(p0a0), bhi(p0a1));
            paH[1] = pack2(bhi(p0b0), bhi(p0b1));
            paH[2] = pack2(bhi(p1a0), bhi(p1a1));
            paH[3] = pack2(bhi(p1b0), bhi(p1b1));
            paL[0] = pack2(p0a0 - bhi(p0a0), p0a1 - bhi(p0a1));
            paL[1] = pack2(p0b0 - bhi(p0b0), p0b1 - bhi(p0b1));
            paL[2] = pack2(p1a0 - bhi(p1a0), p1a1 - bhi(p1a1));
            paL[3] = pack2(p1b0 - bhi(p1b0), p1b1 - bhi(p1b1));

            uint32_t vj = (uint32_t)j * 2304u + voff4;
#pragma unroll
            for (int n = 0; n < 8; n++) {
                uint32_t v4[4];
                ldsm4t(v4, VHa + vj + n * 16);
                mma16816(O[n], paH, v4[0], v4[1]);
                mma16816(O[n], paH, v4[2], v4[3]);
                mma16816(O[n], paL, v4[0], v4[1]);
            }
        }
        __syncthreads();
        cur ^= 1;
    }

    lpa += __shfl_xor_sync(0xffffffffu, lpa, 1);
    lpa += __shfl_xor_sync(0xffffffffu, lpa, 2);
    lpb += __shfl_xor_sync(0xffffffffu, lpb, 1);
    lpb += __shfl_xor_sync(0xffffffffu, lpb, 2);
    const float invla = (lpa > 0.0f) ? 1.0f / lpa : 0.0f;
    const float invlb = (lpb > 0.0f) ? 1.0f / lpb : 0.0f;

    if (lc == 0) {
        d_linv[(b * H_ + h) * N_ + qa] = invla;
        d_linv[(b * H_ + h) * N_ + qb] = invlb;
    }

    float* oa = outp + ((size_t)(b * H_ + h) * N_ + qa) * D_;
    float* ob = outp + ((size_t)(b * H_ + h) * N_ + qb) * D_;
#pragma unroll
    for (int n = 0; n < 8; n++) {
        *(float2*)(oa + n * 8 + 2 * lc) = make_float2(O[n][0] * invla, O[n][1] * invla);
        *(float2*)(ob + n * 8 + 2 * lc) = make_float2(O[n][2] * invlb, O[n][3] * invlb);
    }
}

// ---------------------------------------------------------------------------
// expand+normalize: compact p' -> full pg row (zeros for masked cols)
// ---------------------------------------------------------------------------
__global__ void __launch_bounds__(128) expand_pg_kernel(float* __restrict__ pg) {
    const int row = blockIdx.x;            // (b*HG + hg)*N + q
    const int b = row >> 14;
    const int hg = (row >> 11) & 7;
    const int q = row & 2047;
    const float s = d_linv[(b * H_ + hg) * N_ + q];
    const float* src = d_pgc + (size_t)row * N_;
    float* dst = pg + (size_t)row * N_;
    const int* pos = d_pos + b * N_;
    for (int c0 = threadIdx.x * 4; c0 < N_; c0 += 512) {
        int4 pp = *(const int4*)(pos + c0);
        unsigned int w = d_mb[b * 64 + (c0 >> 5)];
        int sh = c0 & 31;
        float4 o;
        o.x = ((w >> sh) & 1)       ? src[pp.x] * s : 0.0f;
        o.y = ((w >> (sh + 1)) & 1) ? src[pp.y] * s : 0.0f;
        o.z = ((w >> (sh + 2)) & 1) ? src[pp.z] * s : 0.0f;
        o.w = ((w >> (sh + 3)) & 1) ? src[pp.w] * s : 0.0f;
        *(float4*)(dst + c0) = o;
    }
}

__global__ void __launch_bounds__(128) scale_pl_kernel(float* __restrict__ pl) {
    const int row = blockIdx.x;
    const int b = row >> 14;
    const int hl = (row >> 11) & 7;
    const int q = row & 2047;
    const float s = d_linv[(b * H_ + HG + hl) * N_ + q];
    int lo = q - W_; if (lo < 0) lo = 0;
    int hi = q + W_; if (hi > N_ - 1) hi = N_ - 1;
    float* p = pl + (size_t)row * N_;
    for (int c = lo + threadIdx.x; c <= hi; c += 128)
        p[c] *= s;
}

// ---------------------------------------------------------------------------
extern "C" void kernel_launch(void* const* d_in, const int* in_sizes, int n_in,
                              void* d_out, int out_size) {
    const float* Q = (const float*)d_in[0];
    const float* K = (const float*)d_in[1];
    const float* V = (const float*)d_in[2];
    const void* mask = d_in[3];

    float* out = (float*)d_out;
    float* pg = out + (size_t)B_ * H_ * N_ * D_;
    float* pl = pg + (size_t)B_ * HG * N_ * N_;

    static int attr_set = 0;
    if (!attr_set) {
        cudaFuncSetAttribute(gattn_global_kernel, cudaFuncAttributeMaxDynamicSharedMemorySize, SMEM_SZ);
        cudaFuncSetAttribute(gattn_local_kernel, cudaFuncAttributeMaxDynamicSharedMemorySize, SMEM_SZ);
        attr_set = 1;
    }

    prep_mask_kernel<<<1, 256>>>(mask);
    compact_kv_kernel<<<dim3(16, HG, B_), 256>>>(K, V);

    gattn_global_kernel<<<dim3(N_ / 256, HG, B_), 512, SMEM_SZ>>>(Q, out);
    gattn_local_kernel<<<dim3(N_ / 256, HL, B_), 512, SMEM_SZ>>>(Q, K, V, out, pl);

    expand_pg_kernel<<<B_ * HG * N_, 128>>>(pg);
    scale_pl_kernel<<<B_ * HL * N_, 128>>>(pl);
}

// round 9
// speedup vs baseline: 2.7417x; 1.0151x over previous
#include <cuda_runtime.h>
#include <cuda_bf16.h>
#include <stdint.h>

#define B_ 2
#define H_ 16
#define N_ 2048
#define D_ 64
#define HG 8
#define HL 8
#define W_ 64
#define SCALE 0.125f

__device__ unsigned int d_mb[B_ * 64];
__device__ float d_linv[B_ * H_ * N_];
__device__ int d_pos[B_ * N_];
__device__ int d_idx[B_ * N_];
__device__ int d_cnt[B_];
__device__ float d_pgc[(size_t)B_ * HG * N_ * N_];
__device__ __nv_bfloat16 d_kch[(size_t)B_ * HG * N_ * D_];
__device__ __nv_bfloat16 d_kcl[(size_t)B_ * HG * N_ * D_];
__device__ __nv_bfloat16 d_vch[(size_t)B_ * HG * N_ * D_];
__device__ __nv_bfloat16 d_vcl[(size_t)B_ * HG * N_ * D_];

// ---- smem layout (bytes) ----
#define OQH 0u
#define OQL 36864u
#define OBUF 73728u
#define BUFSTRIDE 73728u
#define BKH 0u
#define BKL 18432u
#define BVH 36864u
#define BVL 55296u
#define OMB 221184u
#define SMEM_SZ 221696

__device__ __forceinline__ uint32_t smem_u32(const void* p) {
    uint32_t a;
    asm("{ .reg .u64 t; cvta.to.shared.u64 t, %1; cvt.u32.u64 %0, t; }" : "=r"(a) : "l"(p));
    return a;
}
__device__ __forceinline__ void ldsm4(uint32_t a[4], uint32_t addr) {
    asm volatile("ldmatrix.sync.aligned.m8n8.x4.shared.b16 {%0,%1,%2,%3}, [%4];"
                 : "=r"(a[0]), "=r"(a[1]), "=r"(a[2]), "=r"(a[3]) : "r"(addr));
}
__device__ __forceinline__ void ldsm4t(uint32_t a[4], uint32_t addr) {
    asm volatile("ldmatrix.sync.aligned.m8n8.x4.trans.shared.b16 {%0,%1,%2,%3}, [%4];"
                 : "=r"(a[0]), "=r"(a[1]), "=r"(a[2]), "=r"(a[3]) : "r"(addr));
}
__device__ __forceinline__ void mma16816(float c[4], const uint32_t a[4], uint32_t b0, uint32_t b1) {
    asm volatile("mma.sync.aligned.m16n8k16.row.col.f32.bf16.bf16.f32 "
                 "{%0,%1,%2,%3}, {%4,%5,%6,%7}, {%8,%9}, {%0,%1,%2,%3};"
                 : "+f"(c[0]), "+f"(c[1]), "+f"(c[2]), "+f"(c[3])
                 : "r"(a[0]), "r"(a[1]), "r"(a[2]), "r"(a[3]), "r"(b0), "r"(b1));
}
__device__ __forceinline__ uint32_t pack2(float lo, float hi) {
    __nv_bfloat162 t = __floats2bfloat162_rn(lo, hi);
    return *(uint32_t*)&t;
}
__device__ __forceinline__ float bhi(float x) {
    return __bfloat162float(__float2bfloat16(x));
}
__device__ __forceinline__ void split2(float a, float b, uint32_t& hw, uint32_t& lw) {
    __nv_bfloat16 ha = __float2bfloat16(a);
    float fa = __bfloat162float(ha);
    __nv_bfloat16 hb = __float2bfloat16(b);
    float fb = __bfloat162float(hb);
    hw = (uint32_t)__bfloat16_as_ushort(ha) | ((uint32_t)__bfloat16_as_ushort(hb) << 16);
    lw = (uint32_t)__bfloat16_as_ushort(__float2bfloat16(a - fa)) |
         ((uint32_t)__bfloat16_as_ushort(__float2bfloat16(b - fb)) << 16);
}

// ---------------------------------------------------------------------------
// prep: mask dtype detect, bitmask, per-batch compaction map
// ---------------------------------------------------------------------------
__global__ void prep_mask_kernel(const void* __restrict__ mraw) {
    __shared__ int mode;
    __shared__ int cnt_s[256];
    __shared__ int off_s[256];
    const int t = threadIdx.x;
    if (t == 0) {
        const unsigned int* w = (const unsigned int*)mraw;
        bool ii = true, ff = true;
        for (int i = 0; i < 64; i++) {
            unsigned int v = w[i];
            if (v > 1u) ii = false;
            if (v != 0u && v != 0x3F800000u) ff = false;
        }
        mode = ii ? 1 : (ff ? 2 : 0);
    }
    __syncthreads();
    int m = mode;
    if (t < 128) {
        unsigned int w = 0;
        for (int k = 0; k < 32; k++) {
            int idx = t * 32 + k;
            int v;
            if (m == 1)      v = (((const int*)mraw)[idx] != 0);
            else if (m == 2) v = (((const float*)mraw)[idx] != 0.0f);
            else             v = (((const unsigned char*)mraw)[idx] != 0);
            if (v) w |= 1u << k;
        }
        d_mb[t] = w;
    }
    __syncthreads();
    for (int b = 0; b < B_; b++) {
        unsigned int word = d_mb[b * 64 + (t >> 2)];
        unsigned int byte = (word >> ((t & 3) * 8)) & 0xFFu;
        cnt_s[t] = __popc(byte);
        __syncthreads();
        if (t == 0) {
            int run = 0;
            for (int i = 0; i < 256; i++) { off_s[i] = run; run += cnt_s[i]; }
            d_cnt[b] = run;
        }
        __syncthreads();
        int p = off_s[t];
        for (int k = 0; k < 8; k++) {
            int c = t * 8 + k;
            if ((byte >> k) & 1) {
                d_idx[b * N_ + p] = c;
                d_pos[b * N_ + c] = p;
                p++;
            } else {
                d_pos[b * N_ + c] = 0;
            }
        }
        __syncthreads();
    }
}

// ---------------------------------------------------------------------------
__global__ void __launch_bounds__(256) compact_kv_kernel(const float* __restrict__ K,
                                                         const float* __restrict__ V) {
    const int b = blockIdx.z, h = blockIdx.y, jt = blockIdx.x;
    const int cnt = d_cnt[b];
    const int cnt_pad = (cnt + 127) & ~127;
    const int j0 = jt * 128;
    if (j0 >= cnt_pad) return;
    const size_t obase = (size_t)(b * HG + h) * N_ * D_;
    for (int idx = threadIdx.x; idx < 128 * 16; idx += 256) {
        int r = idx >> 4, c4 = (idx & 15) << 2;
        int j = j0 + r;
        float4 kv = make_float4(0.f, 0.f, 0.f, 0.f);
        float4 vv = make_float4(0.f, 0.f, 0.f, 0.f);
        if (j < cnt) {
            int src = d_idx[b * N_ + j];
            size_t sb = ((size_t)(b * H_ + h) * N_ + src) * D_ + c4;
            kv = *(const float4*)(K + sb);
            vv = *(const float4*)(V + sb);
        }
        size_t off = obase + (size_t)j * D_ + c4;
        uint32_t h01, l01, h23, l23;
        split2(kv.x, kv.y, h01, l01); split2(kv.z, kv.w, h23, l23);
        *(uint2*)(d_kch + off) = make_uint2(h01, h23);
        *(uint2*)(d_kcl + off) = make_uint2(l01, l23);
        split2(vv.x, vv.y, h01, l01); split2(vv.z, vv.w, h23, l23);
        *(uint2*)(d_vch + off) = make_uint2(h01, h23);
        *(uint2*)(d_vcl + off) = make_uint2(l01, l23);
    }
}

__device__ __forceinline__ void loadsplit(const float* __restrict__ src,
                                          __nv_bfloat16* H, __nv_bfloat16* L,
                                          int tid, int n16) {
    for (int idx = tid; idx < n16; idx += 512) {
        int r = idx >> 4, c4 = (idx & 15) << 2;
        float4 v = *(const float4*)(src + r * D_ + c4);
        uint32_t h01, l01, h23, l23;
        split2(v.x, v.y, h01, l01);
        split2(v.z, v.w, h23, l23);
        uint32_t* hp = (uint32_t*)(H + r * 72 + c4);
        uint32_t* lp = (uint32_t*)(L + r * 72 + c4);
        hp[0] = h01; hp[1] = h23;
        lp[0] = l01; lp[1] = l23;
    }
}

__device__ __forceinline__ void loadcopy(const __nv_bfloat16* __restrict__ src,
                                         char* dst, int tid) {
    const uint4* s4 = (const uint4*)src;
    for (int idx = tid; idx < 1024; idx += 512) {
        int r = idx >> 3, c8 = idx & 7;
        uint4 v = s4[r * 8 + c8];
        *(uint4*)(dst + r * 144 + c8 * 16) = v;
    }
}

// ---------------------------------------------------------------------------
// Merged attention: blockIdx.y = head (0-7 global/compact, 8-15 local/banded)
// ---------------------------------------------------------------------------
__global__ void __launch_bounds__(512, 1)
gattn_kernel(const float* __restrict__ Q, const float* __restrict__ K,
             const float* __restrict__ V, float* __restrict__ outp,
             float* __restrict__ pl) {
    extern __shared__ char sm[];
    __nv_bfloat16* QH = (__nv_bfloat16*)(sm + OQH);
    __nv_bfloat16* QL = (__nv_bfloat16*)(sm + OQL);

    const int b = blockIdx.z, h = blockIdx.y, q0 = blockIdx.x * 256;
    const bool loc = (h >= HG);
    const int tid = threadIdx.x, wq = tid >> 5, lane = tid & 31;
    const int q0w = wq * 16;
    const int l7 = lane & 7, l8 = lane & 8, l15 = lane & 15;
    const int lq = lane >> 2, lc = lane & 3;

    const float* Qp = Q + ((size_t)(b * H_ + h) * N_ + q0) * D_;

    const uint32_t QHa = smem_u32(QH), QLa = smem_u32(QL);
    const uint32_t BUFa = smem_u32(sm + OBUF);
    const uint32_t koff4 = (uint32_t)(l7 * 144 + l8 * 2 + (lane & 16) * 72);
    const uint32_t voff4 = (uint32_t)(l15 * 144 + ((lane & 16) ? 18432u : 0u));

    const int qa = q0 + q0w + lq;
    const int qb = qa + 8;
    const int qw0 = q0 + q0w;

    float O[8][4];
#pragma unroll
    for (int n = 0; n < 8; n++)
#pragma unroll
        for (int e = 0; e < 4; e++) O[n][e] = 0.0f;
    float lpa = 0.0f, lpb = 0.0f;

    if (!loc) {
        // ================= GLOBAL (compacted keys) =================
        const int cnt = d_cnt[b];
        const int ktn = (cnt + 127) >> 7;
        const __nv_bfloat16* Kh = d_kch + (size_t)(b * HG + h) * N_ * D_;
        const __nv_bfloat16* Kl = d_kcl + (size_t)(b * HG + h) * N_ * D_;
        const __nv_bfloat16* Vh = d_vch + (size_t)(b * HG + h) * N_ * D_;
        const __nv_bfloat16* Vl = d_vcl + (size_t)(b * HG + h) * N_ * D_;
        float* pra = d_pgc + ((size_t)(b * HG + h) * N_ + q0 + q0w + lq) * N_;
        float* prb = pra + (size_t)8 * N_;

        loadsplit(Qp, QH, QL, tid, 4096);
        {
            char* bb = sm + OBUF;
            loadcopy(Kh, bb + BKH, tid);
            loadcopy(Kl, bb + BKL, tid);
            loadcopy(Vh, bb + BVH, tid);
            loadcopy(Vl, bb + BVL, tid);
        }
        __syncthreads();

        uint32_t aQH[4][4], aQL[4][4];
#pragma unroll
        for (int kk = 0; kk < 4; kk++) {
            uint32_t qo = (uint32_t)((q0w + l15) * 144 + kk * 32 + ((lane & 16) ? 16 : 0));
            ldsm4(aQH[kk], QHa + qo);
            ldsm4(aQL[kk], QLa + qo);
        }

        int cur = 0;
        for (int kt = 0; kt < ktn; kt++) {
            if (kt + 1 < ktn) {
                char* bb = sm + OBUF + (uint32_t)(cur ^ 1) * BUFSTRIDE;
                size_t t0 = (size_t)(kt + 1) * 128 * D_;
                loadcopy(Kh + t0, bb + BKH, tid);
                loadcopy(Kl + t0, bb + BKL, tid);
                loadcopy(Vh + t0, bb + BVH, tid);
                loadcopy(Vl + t0, bb + BVL, tid);
            }
            const uint32_t KHa = BUFa + (uint32_t)cur * BUFSTRIDE;
            const uint32_t KLa = KHa + BKL;
            const uint32_t VHa = KHa + BVH;

#pragma unroll
            for (int j = 0; j < 8; j++) {
                const int ct = kt * 128 + j * 16 + 2 * lc;
                float c0[4] = {0, 0, 0, 0}, c1[4] = {0, 0, 0, 0};
                uint32_t jo = (uint32_t)j * 2304u + koff4;
#pragma unroll
                for (int kk = 0; kk < 4; kk++) {
                    uint32_t bH[4], bL[4];
                    ldsm4(bH, KHa + jo + kk * 32);
                    ldsm4(bL, KLa + jo + kk * 32);
                    mma16816(c0, aQH[kk], bH[0], bH[1]);
                    mma16816(c0, aQH[kk], bL[0], bL[1]);
                    mma16816(c0, aQL[kk], bH[0], bH[1]);
                    mma16816(c1, aQH[kk], bH[2], bH[3]);
                    mma16816(c1, aQH[kk], bL[2], bL[3]);
                    mma16816(c1, aQL[kk], bH[2], bH[3]);
                }
                bool m0 = (ct < cnt), m1 = (ct + 1 < cnt);
                bool m8 = (ct + 8 < cnt), m9 = (ct + 9 < cnt);
                float p0a0 = m0 ? __expf(c0[0] * SCALE) : 0.0f;
                float p0a1 = m1 ? __expf(c0[1] * SCALE) : 0.0f;
                float p0b0 = m0 ? __expf(c0[2] * SCALE) : 0.0f;
                float p0b1 = m1 ? __expf(c0[3] * SCALE) : 0.0f;
                float p1a0 = m8 ? __expf(c1[0] * SCALE) : 0.0f;
                float p1a1 = m9 ? __expf(c1[1] * SCALE) : 0.0f;
                float p1b0 = m8 ? __expf(c1[2] * SCALE) : 0.0f;
                float p1b1 = m9 ? __expf(c1[3] * SCALE) : 0.0f;

                lpa += (p0a0 + p0a1) + (p1a0 + p1a1);
                lpb += (p0b0 + p0b1) + (p1b0 + p1b1);

                *(float2*)(pra + ct)     = make_float2(p0a0, p0a1);
                *(float2*)(pra + ct + 8) = make_float2(p1a0, p1a1);
                *(float2*)(prb + ct)     = make_float2(p0b0, p0b1);
                *(float2*)(prb + ct + 8) = make_float2(p1b0, p1b1);

                uint32_t paH[4], paL[4];
                paH[0] = pack2(bhi(p0a0), bhi(p0a1));
                paH[1] = pack2(bhi(p0b0), bhi(p0b1));
                paH[2] = pack2(bhi(p1a0), bhi(p1a1));
                paH[3] = pack2(bhi(p1b0), bhi(p1b1));
                paL[0] = pack2(p0a0 - bhi(p0a0), p0a1 - bhi(p0a1));
                paL[1] = pack2(p0b0 - bhi(p0b0), p0b1 - bhi(p0b1));
                paL[2] = pack2(p1a0 - bhi(p1a0), p1a1 - bhi(p1a1));
                paL[3] = pack2(p1b0 - bhi(p1b0), p1b1 - bhi(p1b1));

                uint32_t vj = (uint32_t)j * 2304u + voff4;
#pragma unroll
                for (int n = 0; n < 8; n++) {
                    uint32_t v4[4];
                    ldsm4t(v4, VHa + vj + n * 16);
                    mma16816(O[n], paH, v4[0], v4[1]);
                    mma16816(O[n], paH, v4[2], v4[3]);
                    mma16816(O[n], paL, v4[0], v4[1]);
                }
            }
            __syncthreads();
            cur ^= 1;
        }
    } else {
        // ================= LOCAL (banded) =================
        unsigned int* mbS = (unsigned int*)(sm + OMB);
        const int hy = h - HG;
        const float* Kp = K + ((size_t)(b * H_ + h)) * N_ * D_;
        const float* Vp = V + ((size_t)(b * H_ + h)) * N_ * D_;
        float* prowbase = pl + ((size_t)(b * HL + hy) * N_ + q0) * N_;
        float* pra = prowbase + (size_t)(q0w + lq) * N_;
        float* prb = pra + (size_t)8 * N_;

        int klo = q0 - W_; if (klo < 0) klo = 0;
        int khi = q0 + 255 + W_; if (khi > N_ - 1) khi = N_ - 1;
        const int ktlo = klo >> 7, kthi = khi >> 7;
        {
            float4 z = make_float4(0.f, 0.f, 0.f, 0.f);
            for (int kt = 0; kt < 16; kt++) {
                if (kt >= ktlo && kt <= kthi) continue;
                for (int idx = tid; idx < 256 * 32; idx += 512) {
                    int r = idx >> 5, c4 = (idx & 31) << 2;
                    *(float4*)(prowbase + (size_t)r * N_ + kt * 128 + c4) = z;
                }
            }
        }

        if (tid < 64) mbS[tid] = d_mb[b * 64 + tid];
        loadsplit(Qp, QH, QL, tid, 4096);
        {
            char* bb = sm + OBUF;
            loadsplit(Kp + (size_t)ktlo * 128 * D_, (__nv_bfloat16*)(bb + BKH),
                      (__nv_bfloat16*)(bb + BKL), tid, 2048);
            loadsplit(Vp + (size_t)ktlo * 128 * D_, (__nv_bfloat16*)(bb + BVH),
                      (__nv_bfloat16*)(bb + BVL), tid, 2048);
        }
        __syncthreads();

        uint32_t aQH[4][4], aQL[4][4];
#pragma unroll
        for (int kk = 0; kk < 4; kk++) {
            uint32_t qo = (uint32_t)((q0w + l15) * 144 + kk * 32 + ((lane & 16) ? 16 : 0));
            ldsm4(aQH[kk], QHa + qo);
            ldsm4(aQL[kk], QLa + qo);
        }

        int cur = 0;
        for (int kt = ktlo; kt <= kthi; kt++) {
            if (kt < kthi) {
                char* bb = sm + OBUF + (uint32_t)(cur ^ 1) * BUFSTRIDE;
                loadsplit(Kp + (size_t)(kt + 1) * 128 * D_, (__nv_bfloat16*)(bb + BKH),
                          (__nv_bfloat16*)(bb + BKL), tid, 2048);
                loadsplit(Vp + (size_t)(kt + 1) * 128 * D_, (__nv_bfloat16*)(bb + BVH),
                          (__nv_bfloat16*)(bb + BVL), tid, 2048);
            }
            const uint32_t KHa = BUFa + (uint32_t)cur * BUFSTRIDE;
            const uint32_t KLa = KHa + BKL;
            const uint32_t VHa = KHa + BVH;

            unsigned int mw[4];
#pragma unroll
            for (int i = 0; i < 4; i++) mw[i] = mbS[kt * 4 + i];
#pragma unroll
            for (int j = 0; j < 8; j++) {
                const int k0j = kt * 128 + j * 16;
                const int ct = k0j + 2 * lc;
                if (!((k0j <= qw0 + 79) && (k0j + 15 >= qw0 - 64))) {
                    float2 z2 = make_float2(0.f, 0.f);
                    *(float2*)(pra + ct) = z2; *(float2*)(pra + ct + 8) = z2;
                    *(float2*)(prb + ct) = z2; *(float2*)(prb + ct + 8) = z2;
                    continue;
                }
                float c0[4] = {0, 0, 0, 0}, c1[4] = {0, 0, 0, 0};
                uint32_t jo = (uint32_t)j * 2304u + koff4;
#pragma unroll
                for (int kk = 0; kk < 4; kk++) {
                    uint32_t bH[4], bL[4];
                    ldsm4(bH, KHa + jo + kk * 32);
                    ldsm4(bL, KLa + jo + kk * 32);
                    mma16816(c0, aQH[kk], bH[0], bH[1]);
                    mma16816(c0, aQH[kk], bL[0], bL[1]);
                    mma16816(c0, aQL[kk], bH[0], bH[1]);
                    mma16816(c1, aQH[kk], bH[2], bH[3]);
                    mma16816(c1, aQH[kk], bL[2], bL[3]);
                    mma16816(c1, aQL[kk], bH[2], bH[3]);
                }
                unsigned int w = mw[j >> 1];
                int sh = (j & 1) * 16 + 2 * lc;
                bool m0 = (w >> sh) & 1, m1 = (w >> (sh + 1)) & 1;
                bool m8 = (w >> (sh + 8)) & 1, m9 = (w >> (sh + 9)) & 1;
                bool ba0 = ((unsigned)(ct - qa + 64) <= 128u);
                bool ba1 = ((unsigned)(ct + 1 - qa + 64) <= 128u);
                bool bb0 = ((unsigned)(ct - qb + 64) <= 128u);
                bool bb1 = ((unsigned)(ct + 1 - qb + 64) <= 128u);
                bool ba8 = ((unsigned)(ct + 8 - qa + 64) <= 128u);
                bool ba9 = ((unsigned)(ct + 9 - qa + 64) <= 128u);
                bool bb8 = ((unsigned)(ct + 8 - qb + 64) <= 128u);
                bool bb9 = ((unsigned)(ct + 9 - qb + 64) <= 128u);

                float p0a0 = (m0 && ba0) ? __expf(c0[0] * SCALE) : 0.0f;
                float p0a1 = (m1 && ba1) ? __expf(c0[1] * SCALE) : 0.0f;
                float p0b0 = (m0 && bb0) ? __expf(c0[2] * SCALE) : 0.0f;
                float p0b1 = (m1 && bb1) ? __expf(c0[3] * SCALE) : 0.0f;
                float p1a0 = (m8 && ba8) ? __expf(c1[0] * SCALE) : 0.0f;
                float p1a1 = (m9 && ba9) ? __expf(c1[1] * SCALE) : 0.0f;
                float p1b0 = (m8 && bb8) ? __expf(c1[2] * SCALE) : 0.0f;
                float p1b1 = (m9 && bb9) ? __expf(c1[3] * SCALE) : 0.0f;

                lpa += (p0a0 + p0a1) + (p1a0 + p1a1);
                lpb += (p0b0 + p0b1) + (p1b0 + p1b1);

                *(float2*)(pra + ct)     = make_float2(p0a0, p0a1);
                *(float2*)(pra + ct + 8) = make_float2(p1a0, p1a1);
                *(float2*)(prb + ct)     = make_float2(p0b0, p0b1);
                *(float2*)(prb + ct + 8) = make_float2(p1b0, p1b1);

                uint32_t paH[4], paL[4];
                paH[0] = pack2(bhi(p0a0), bhi(p0a1));
                paH[1] = pack2(bhi(p0b0), bhi(p0b1));
                paH[2] = pack2(bhi(p1a0), bhi(p1a1));
                paH[3] = pack2(bhi(p1b0), bhi(p1b1));
                paL[0] = pack2(p0a0 - bhi(p0a0), p0a1 - bhi(p0a1));
                paL[1] = pack2(p0b0 - bhi(p0b0), p0b1 - bhi(p0b1));
                paL[2] = pack2(p1a0 - bhi(p1a0), p1a1 - bhi(p1a1));
                paL[3] = pack2(p1b0 - bhi(p1b0), p1b1 - bhi(p1b1));

                uint32_t vj = (uint32_t)j * 2304u + voff4;
#pragma unroll
                for (int n = 0; n < 8; n++) {
                    uint32_t v4[4];
                    ldsm4t(v4, VHa + vj + n * 16);
                    mma16816(O[n], paH, v4[0], v4[1]);
                    mma16816(O[n], paH, v4[2], v4[3]);
                    mma16816(O[n], paL, v4[0], v4[1]);
                }
            }
            __syncthreads();
            cur ^= 1;
        }
    }

    lpa += __shfl_xor_sync(0xffffffffu, lpa, 1);
    lpa += __shfl_xor_sync(0xffffffffu, lpa, 2);
    lpb += __shfl_xor_sync(0xffffffffu, lpb, 1);
    lpb += __shfl_xor_sync(0xffffffffu, lpb, 2);
    const float invla = (lpa > 0.0f) ? 1.0f / lpa : 0.0f;
    const float invlb = (lpb > 0.0f) ? 1.0f / lpb : 0.0f;

    if (lc == 0) {
        d_linv[(b * H_ + h) * N_ + qa] = invla;
        d_linv[(b * H_ + h) * N_ + qb] = invlb;
    }

    float* oa = outp + ((size_t)(b * H_ + h) * N_ + qa) * D_;
    float* ob = outp + ((size_t)(b * H_ + h) * N_ + qb) * D_;
#pragma unroll
    for (int n = 0; n < 8; n++) {
        *(float2*)(oa + n * 8 + 2 * lc) = make_float2(O[n][0] * invla, O[n][1] * invla);
        *(float2*)(ob + n * 8 + 2 * lc) = make_float2(O[n][2] * invlb, O[n][3] * invlb);
    }
}

// ---------------------------------------------------------------------------
// merged epilogue: rows [0,32768) = expand+normalize pg; [32768,65536) = scale pl band
// ---------------------------------------------------------------------------
__global__ void __launch_bounds__(128) epilogue_kernel(float* __restrict__ pg,
                                                       float* __restrict__ pl) {
    int row = blockIdx.x;
    if (row < B_ * HG * N_) {
        const int b = row >> 14;
        const int hg = (row >> 11) & 7;
        const int q = row & 2047;
        const float s = d_linv[(b * H_ + hg) * N_ + q];
        const float* src = d_pgc + (size_t)row * N_;
        float* dst = pg + (size_t)row * N_;
        const int* pos = d_pos + b * N_;
        for (int c0 = threadIdx.x * 4; c0 < N_; c0 += 512) {
            int4 pp = *(const int4*)(pos + c0);
            unsigned int w = d_mb[b * 64 + (c0 >> 5)];
            int sh = c0 & 31;
            float4 o;
            o.x = ((w >> sh) & 1)       ? src[pp.x] * s : 0.0f;
            o.y = ((w >> (sh + 1)) & 1) ? src[pp.y] * s : 0.0f;
            o.z = ((w >> (sh + 2)) & 1) ? src[pp.z] * s : 0.0f;
            o.w = ((w >> (sh + 3)) & 1) ? src[pp.w] * s : 0.0f;
            *(float4*)(dst + c0) = o;
        }
    } else {
        row -= B_ * HG * N_;
        const int b = row >> 14;
        const int hl = (row >> 11) & 7;
        const int q = row & 2047;
        const float s = d_linv[(b * H_ + HG + hl) * N_ + q];
        int lo = q - W_; if (lo < 0) lo = 0;
        int hi = q + W_; if (hi > N_ - 1) hi = N_ - 1;
        float* p = pl + (size_t)row * N_;
        for (int c = lo + threadIdx.x; c <= hi; c += 128)
            p[c] *= s;
    }
}

// ---------------------------------------------------------------------------
extern "C" void kernel_launch(void* const* d_in, const int* in_sizes, int n_in,
                              void* d_out, int out_size) {
    const float* Q = (const float*)d_in[0];
    const float* K = (const float*)d_in[1];
    const float* V = (const float*)d_in[2];
    const void* mask = d_in[3];

    float* out = (float*)d_out;
    float* pg = out + (size_t)B_ * H_ * N_ * D_;
    float* pl = pg + (size_t)B_ * HG * N_ * N_;

    static int attr_set = 0;
    if (!attr_set) {
        cudaFuncSetAttribute(gattn_kernel, cudaFuncAttributeMaxDynamicSharedMemorySize, SMEM_SZ);
        attr_set = 1;
    }

    prep_mask_kernel<<<1, 256>>>(mask);
    compact_kv_kernel<<<dim3(16, HG, B_), 256>>>(K, V);

    gattn_kernel<<<dim3(N_ / 256, H_, B_), 512, SMEM_SZ>>>(Q, K, V, out, pl);

    epilogue_kernel<<<2 * B_ * HG * N_, 128>>>(pg, pl);
}